// round 1
// baseline (speedup 1.0000x reference)
#include <cuda_runtime.h>
#include <math.h>

#define B_SZ 8192
#define D_SZ 128
#define BM 64
#define BN 128
#define SROW 132   // padded smem row stride (floats): keeps float4 alignment, breaks bank conflicts

__device__ float g_sq[B_SZ];
__device__ float g_ce[B_SZ];
__device__ float g_trip[B_SZ];
__device__ int   g_is64;

// ---------- packed fp32x2 helpers (Blackwell) ----------
__device__ __forceinline__ unsigned long long pk2(float lo, float hi) {
    unsigned long long r;
    asm("mov.b64 %0, {%1, %2};" : "=l"(r) : "f"(lo), "f"(hi));
    return r;
}
__device__ __forceinline__ unsigned long long ffma2(unsigned long long a, unsigned long long b,
                                                    unsigned long long c) {
    unsigned long long d;
    asm("fma.rn.f32x2 %0, %1, %2, %3;" : "=l"(d) : "l"(a), "l"(b), "l"(c));
    return d;
}
__device__ __forceinline__ float2 upk2(unsigned long long v) {
    float lo, hi;
    asm("mov.b64 {%0, %1}, %2;" : "=f"(lo), "=f"(hi) : "l"(v));
    return make_float2(lo, hi);
}

// ---------- K0: detect int64 vs int32 targets ----------
__global__ void detect_kernel(const int* __restrict__ t32) {
    __shared__ int sred[256];
    int tid = threadIdx.x;
    int v = 0;
    for (int i = tid; i < B_SZ / 2; i += 256) v |= t32[2 * i + 1];
    sred[tid] = v;
    __syncthreads();
    for (int s = 128; s; s >>= 1) {
        if (tid < s) sred[tid] |= sred[tid + s];
        __syncthreads();
    }
    if (tid == 0) g_is64 = (sred[0] == 0) ? 1 : 0;
}

// ---------- K1: per-row sum-of-squares + cross entropy ----------
__global__ void rowstats_kernel(const float* __restrict__ logits, const void* __restrict__ targets) {
    int lane = threadIdx.x & 31;
    int row = (blockIdx.x << 3) + (threadIdx.x >> 5);
    float4 v = reinterpret_cast<const float4*>(logits)[row * 32 + lane];
    float ss = fmaf(v.x, v.x, fmaf(v.y, v.y, fmaf(v.z, v.z, v.w * v.w)));
    float mx = fmaxf(fmaxf(v.x, v.y), fmaxf(v.z, v.w));
#pragma unroll
    for (int o = 16; o; o >>= 1) {
        ss += __shfl_xor_sync(0xffffffffu, ss, o);
        mx = fmaxf(mx, __shfl_xor_sync(0xffffffffu, mx, o));
    }
    float se = expf(v.x - mx) + expf(v.y - mx) + expf(v.z - mx) + expf(v.w - mx);
#pragma unroll
    for (int o = 16; o; o >>= 1) se += __shfl_xor_sync(0xffffffffu, se, o);
    int t = g_is64 ? (int)((const long long*)targets)[row] : ((const int*)targets)[row];
    int c = t & 3;
    float tv = (c == 0) ? v.x : (c == 1) ? v.y : (c == 2) ? v.z : v.w;
    tv = __shfl_sync(0xffffffffu, tv, t >> 2);
    if (lane == 0) {
        g_sq[row] = ss;
        g_ce[row] = mx + logf(se) - tv;
    }
}

// ---------- K2: fused Gram + batch-hard triplet mining ----------
// grid 128 blocks (64 anchors each), 128 threads: ty=tid/8 owns 4 anchors,
// tx=tid%8 owns 16 interleaved cols (tx + 8*M). acc = 4 anchors x 8 f32x2-pairs.
extern __shared__ float sdyn[];

__global__ void __launch_bounds__(128, 1)
triplet_kernel(const float* __restrict__ X, const void* __restrict__ targets) {
    float* As = sdyn;             // [BM][SROW]
    float* Bs = sdyn + BM * SROW; // [BN][SROW]
    __shared__ float s_sqj[BN];
    __shared__ int   s_tj[BN];
    __shared__ float s_sqa[BM];
    __shared__ int   s_ta[BM];
    __shared__ float s_redm[BM][8];
    __shared__ float s_redn[BM][8];

    const int tid = threadIdx.x;
    const int tx = tid & 7;
    const int ty = tid >> 3;
    const int i0 = blockIdx.x * BM;
    const int is64 = g_is64;

    // fill anchor tile (coalesced LDG.128 -> conflict-free STS.128)
#pragma unroll
    for (int e = tid; e < BM * 32; e += 128) {
        int r = e >> 5, q = e & 31;
        float4 v = reinterpret_cast<const float4*>(X)[(i0 + r) * 32 + q];
        *reinterpret_cast<float4*>(&As[r * SROW + (q << 2)]) = v;
    }
    if (tid < BM) {
        s_sqa[tid] = g_sq[i0 + tid];
        s_ta[tid] = is64 ? (int)((const long long*)targets)[i0 + tid]
                         : ((const int*)targets)[i0 + tid];
    }
    __syncthreads();

    int ta[4];
    float runm[4], runn[4];
#pragma unroll
    for (int ii = 0; ii < 4; ii++) {
        ta[ii] = s_ta[ty * 4 + ii];
        runm[ii] = -INFINITY;
        runn[ii] = INFINITY;
    }

    for (int jt = 0; jt < B_SZ / BN; jt++) {
        const int j0 = jt * BN;
#pragma unroll
        for (int e = tid; e < BN * 32; e += 128) {
            int r = e >> 5, q = e & 31;
            float4 v = reinterpret_cast<const float4*>(X)[(j0 + r) * 32 + q];
            *reinterpret_cast<float4*>(&Bs[r * SROW + (q << 2)]) = v;
        }
        if (tid < BN) {
            s_sqj[tid] = g_sq[j0 + tid];
            s_tj[tid] = is64 ? (int)((const long long*)targets)[j0 + tid]
                             : ((const int*)targets)[j0 + tid];
        }
        __syncthreads();

        unsigned long long acc[4][8];
#pragma unroll
        for (int ii = 0; ii < 4; ii++)
#pragma unroll
            for (int p = 0; p < 8; p++) acc[ii][p] = 0ULL;

        const float* pa = &As[(ty * 4) * SROW];
        const float* pb = &Bs[tx * SROW];

#pragma unroll 2
        for (int k0 = 0; k0 < D_SZ; k0 += 4) {
            float a[4][4];
#pragma unroll
            for (int ii = 0; ii < 4; ii++) {
                float4 t4 = *reinterpret_cast<const float4*>(pa + ii * SROW + k0);
                a[ii][0] = t4.x; a[ii][1] = t4.y; a[ii][2] = t4.z; a[ii][3] = t4.w;
            }
#pragma unroll
            for (int h = 0; h < 2; h++) {
                float b[8][4];
#pragma unroll
                for (int m = 0; m < 8; m++) {
                    float4 t4 = *reinterpret_cast<const float4*>(
                        pb + (h * 8 + m) * (8 * SROW) + k0);
                    b[m][0] = t4.x; b[m][1] = t4.y; b[m][2] = t4.z; b[m][3] = t4.w;
                }
#pragma unroll
                for (int q = 0; q < 4; q++) {
                    unsigned long long bp[4];
#pragma unroll
                    for (int p = 0; p < 4; p++) bp[p] = pk2(b[2 * p][q], b[2 * p + 1][q]);
#pragma unroll
                    for (int ii = 0; ii < 4; ii++) {
                        unsigned long long ap = pk2(a[ii][q], a[ii][q]);
#pragma unroll
                        for (int p = 0; p < 4; p++)
                            acc[ii][h * 4 + p] = ffma2(ap, bp[p], acc[ii][h * 4 + p]);
                    }
                }
            }
        }

        // epilogue: val = sq_j - 2*dot; pos if same class (includes diagonal, like ref)
#pragma unroll
        for (int ii = 0; ii < 4; ii++) {
#pragma unroll
            for (int P = 0; P < 8; P++) {
                float2 d = upk2(acc[ii][P]);
                int M0 = ((P >> 2) << 3) + ((P & 3) << 1);
                int c0 = tx + (M0 << 3);
                int c1 = c0 + 8;
                float v0 = fmaf(-2.0f, d.x, s_sqj[c0]);
                float v1 = fmaf(-2.0f, d.y, s_sqj[c1]);
                if (s_tj[c0] == ta[ii]) runm[ii] = fmaxf(runm[ii], v0);
                else                    runn[ii] = fminf(runn[ii], v0);
                if (s_tj[c1] == ta[ii]) runm[ii] = fmaxf(runm[ii], v1);
                else                    runn[ii] = fminf(runn[ii], v1);
            }
        }
        __syncthreads();  // guard Bs/s_sqj/s_tj before next tile's fill
    }

    // cross-tx reduce per anchor
#pragma unroll
    for (int ii = 0; ii < 4; ii++) {
        s_redm[ty * 4 + ii][tx] = runm[ii];
        s_redn[ty * 4 + ii][tx] = runn[ii];
    }
    __syncthreads();
    if (tid < BM) {
        float mm = -INFINITY, nn = INFINITY;
#pragma unroll
        for (int t = 0; t < 8; t++) {
            mm = fmaxf(mm, s_redm[tid][t]);
            nn = fminf(nn, s_redn[tid][t]);
        }
        float sqi = s_sqa[tid];
        float dap = sqrtf(fmaxf(sqi + mm, 1e-12f));
        float dan = sqrtf(fmaxf(sqi + nn, 1e-12f));
        g_trip[i0 + tid] = fmaxf(dap - dan + 0.3f, 0.0f);
    }
}

// ---------- K3: reductions + Lambert-W + final scalar ----------
__global__ void finalize_kernel(float* __restrict__ out) {
    __shared__ double rc[256], rt[256];
    int tid = threadIdx.x;
    double sc = 0.0, st = 0.0;
    for (int i = tid; i < B_SZ; i += 256) {
        sc += (double)g_ce[i];
        st += (double)g_trip[i];
    }
    rc[tid] = sc; rt[tid] = st;
    __syncthreads();
    for (int s = 128; s; s >>= 1) {
        if (tid < s) { rc[tid] += rc[tid + s]; rt[tid] += rt[tid + s]; }
        __syncthreads();
    }
    if (tid == 0) {
        const double LAM = 0.25;
        const double TAU = log(128.0);
        double ce = rc[0] / (double)B_SZ;
        double l  = rt[0] / (double)B_SZ;
        double e1 = exp(1.0);
        double z = 0.5 * fmax(-2.0 / e1, (l - TAU) / LAM);
        // lambertw, principal branch, Halley x10 (mirrors reference)
        double pv = sqrt(fmax(2.0 * (e1 * z + 1.0), 0.0));
        double wn = -1.0 + pv - pv * pv / 3.0 + (11.0 / 72.0) * pv * pv * pv;
        double w = (z < 0.0) ? wn : log1p(fmax(z, 0.0));
#pragma unroll
        for (int it = 0; it < 10; it++) {
            double ew = exp(w);
            double f = w * ew - z;
            double wp1 = w + 1.0;
            w = w - f / (ew * wp1 - (w + 2.0) * f / (2.0 * wp1));
        }
        double sigma = exp(-w);
        double ls = log(sigma);
        double loss = (ce - TAU) * sigma + LAM * ls * ls;
        out[0] = (float)(loss / (double)B_SZ);
    }
}

extern "C" void kernel_launch(void* const* d_in, const int* in_sizes, int n_in,
                              void* d_out, int out_size) {
    const float* logits = (const float*)d_in[0];
    const void* targets = d_in[1];
    float* out = (float*)d_out;
    (void)in_sizes; (void)n_in; (void)out_size;

    const int smem_bytes = (BM + BN) * SROW * (int)sizeof(float);
    cudaFuncSetAttribute(triplet_kernel, cudaFuncAttributeMaxDynamicSharedMemorySize, smem_bytes);

    detect_kernel<<<1, 256>>>((const int*)targets);
    rowstats_kernel<<<B_SZ / 8, 256>>>(logits, targets);
    triplet_kernel<<<B_SZ / BM, 128, smem_bytes>>>(logits, targets);
    finalize_kernel<<<1, 256>>>(out);
}

// round 3
// speedup vs baseline: 4.6246x; 4.6246x over previous
#include <cuda_runtime.h>
#include <math.h>
#include <stdint.h>

#define B_SZ 8192
#define D_SZ 128
#define TM 128          // anchors per CTA
#define TN 128          // j-cols per tile
#define NSPLIT 2
#define JT_PER (B_SZ / NSPLIT / TN)   // 32 tiles
#define BSTRIDE 132     // padded B smem row stride (floats)
#define BUF_ELEMS (TN * BSTRIDE)

__device__ float  g_sq[B_SZ];
__device__ float  g_ce[B_SZ];
__device__ float  g_pm[NSPLIT * B_SZ];
__device__ float  g_pn[NSPLIT * B_SZ];
__device__ double g_part_tr[16];
__device__ double g_part_ce[16];
__device__ int    g_is64;

// ---------------- PTX helpers (baseline ISA only, no 'a' features) ----------------
__device__ __forceinline__ unsigned tf32r(float x) {
    unsigned y;
    asm("cvt.rna.tf32.f32 %0, %1;" : "=r"(y) : "f"(x));
    return y;
}

__device__ __forceinline__ void mma_tf32(float d[4], const unsigned a[4],
                                         unsigned b0, unsigned b1) {
    asm volatile(
        "mma.sync.aligned.m16n8k8.row.col.f32.tf32.tf32.f32 "
        "{%0,%1,%2,%3}, {%4,%5,%6,%7}, {%8,%9}, {%0,%1,%2,%3};"
        : "+f"(d[0]), "+f"(d[1]), "+f"(d[2]), "+f"(d[3])
        : "r"(a[0]), "r"(a[1]), "r"(a[2]), "r"(a[3]), "r"(b0), "r"(b1));
}

__device__ __forceinline__ unsigned smem_u32(const void* p) {
    unsigned a;
    asm("{ .reg .u64 t; cvta.to.shared.u64 t, %1; cvt.u32.u64 %0, t; }" : "=r"(a) : "l"(p));
    return a;
}
__device__ __forceinline__ void cp16(unsigned dst, const void* src) {
    asm volatile("cp.async.cg.shared.global [%0], [%1], 16;" :: "r"(dst), "l"(src) : "memory");
}
#define CP_COMMIT() asm volatile("cp.async.commit_group;" ::: "memory")
#define CP_WAIT1()  asm volatile("cp.async.wait_group 1;" ::: "memory")
#define CP_WAIT0()  asm volatile("cp.async.wait_group 0;" ::: "memory")

// ---------- K0: detect int64 vs int32 targets ----------
__global__ void detect_kernel(const int* __restrict__ t32) {
    __shared__ int sred[256];
    int tid = threadIdx.x;
    int v = 0;
    for (int i = tid; i < B_SZ / 2; i += 256) v |= t32[2 * i + 1];
    sred[tid] = v;
    __syncthreads();
    for (int s = 128; s; s >>= 1) {
        if (tid < s) sred[tid] |= sred[tid + s];
        __syncthreads();
    }
    if (tid == 0) g_is64 = (sred[0] == 0) ? 1 : 0;
}

// ---------- K1: per-row sum-of-squares + cross entropy ----------
__global__ void rowstats_kernel(const float* __restrict__ logits, const void* __restrict__ targets) {
    int lane = threadIdx.x & 31;
    int row = (blockIdx.x << 3) + (threadIdx.x >> 5);
    float4 v = reinterpret_cast<const float4*>(logits)[row * 32 + lane];
    float ss = fmaf(v.x, v.x, fmaf(v.y, v.y, fmaf(v.z, v.z, v.w * v.w)));
    float mx = fmaxf(fmaxf(v.x, v.y), fmaxf(v.z, v.w));
#pragma unroll
    for (int o = 16; o; o >>= 1) {
        ss += __shfl_xor_sync(0xffffffffu, ss, o);
        mx = fmaxf(mx, __shfl_xor_sync(0xffffffffu, mx, o));
    }
    float se = expf(v.x - mx) + expf(v.y - mx) + expf(v.z - mx) + expf(v.w - mx);
#pragma unroll
    for (int o = 16; o; o >>= 1) se += __shfl_xor_sync(0xffffffffu, se, o);
    int t = g_is64 ? (int)((const long long*)targets)[row] : ((const int*)targets)[row];
    int c = t & 3;
    float tv = (c == 0) ? v.x : (c == 1) ? v.y : (c == 2) ? v.z : v.w;
    tv = __shfl_sync(0xffffffffu, tv, t >> 2);
    if (lane == 0) {
        g_sq[row] = ss;
        g_ce[row] = mx + logf(se) - tv;
    }
}

// ---------- K2: mma.sync tf32 Gram + fused batch-hard mining ----------
// 128 CTAs: strip = bx>>1 (128 anchors), half = bx&1 (4096 cols, 32 tiles).
// 8 warps: warp_m=(wid&3)*32 rows, warp_n=(wid>>2)*64 cols. A in registers.
extern __shared__ float s_b[];   // [2][TN][BSTRIDE]

__global__ void __launch_bounds__(256, 1)
triplet_mma_kernel(const float* __restrict__ X, const void* __restrict__ targets) {
    __shared__ __align__(16) uint2 s_sjt[2][TN];   // {sq bits, target}
    __shared__ int   s_ta[TM];
    __shared__ float s_redm[2][TM], s_redn[2][TM];

    const int tid  = threadIdx.x;
    const int wid  = tid >> 5;
    const int lane = tid & 31;
    const int warp_m = (wid & 3) * 32;
    const int wcol   = wid >> 2;
    const int warp_n = wcol * 64;
    const int strip = blockIdx.x >> 1;
    const int half  = blockIdx.x & 1;
    const int i0    = strip * TM;
    const int jbase = half * (B_SZ / NSPLIT);
    const int is64  = g_is64;

    // ---- prefetch tile 0 (B data + sq/targets) ----
    {
        const int j0 = jbase;
        unsigned sb = smem_u32(s_b);
#pragma unroll
        for (int e = tid; e < TN * 32; e += 256) {
            int n = e >> 5, q = e & 31;
            cp16(sb + (unsigned)(n * BSTRIDE + q * 4) * 4u, &X[(j0 + n) * D_SZ + q * 4]);
        }
        if (tid < TN) {
            int t = is64 ? (int)((const long long*)targets)[j0 + tid]
                         : ((const int*)targets)[j0 + tid];
            s_sjt[0][tid] = make_uint2(__float_as_uint(g_sq[j0 + tid]), (unsigned)t);
        }
        CP_COMMIT();
    }
    if (tid < TM)
        s_ta[tid] = is64 ? (int)((const long long*)targets)[i0 + tid]
                         : ((const int*)targets)[i0 + tid];

    // ---- load A fragments into registers (tf32-rounded), fixed for all tiles ----
    unsigned a_[16][2][4];
    {
        const int r0 = i0 + warp_m + (lane >> 2);
        const int c0 = lane & 3;
#pragma unroll
        for (int s = 0; s < 16; s++) {
#pragma unroll
            for (int mf = 0; mf < 2; mf++) {
                int r = r0 + mf * 16;
                a_[s][mf][0] = tf32r(__ldg(&X[r * D_SZ + s * 8 + c0]));
                a_[s][mf][1] = tf32r(__ldg(&X[(r + 8) * D_SZ + s * 8 + c0]));
                a_[s][mf][2] = tf32r(__ldg(&X[r * D_SZ + s * 8 + c0 + 4]));
                a_[s][mf][3] = tf32r(__ldg(&X[(r + 8) * D_SZ + s * 8 + c0 + 4]));
            }
        }
    }

    int ta2[2][2];
#pragma unroll
    for (int mf = 0; mf < 2; mf++)
#pragma unroll
        for (int h = 0; h < 2; h++) { ta2[mf][h] = 0; }
    __syncthreads();   // s_ta visible
#pragma unroll
    for (int mf = 0; mf < 2; mf++)
#pragma unroll
        for (int h = 0; h < 2; h++)
            ta2[mf][h] = s_ta[warp_m + mf * 16 + (lane >> 2) + 8 * h];

    float runm[4], runn[4];
#pragma unroll
    for (int s = 0; s < 4; s++) { runm[s] = -INFINITY; runn[s] = INFINITY; }

    for (int jt = 0; jt < JT_PER; jt++) {
        const int cur = jt & 1, nxt = cur ^ 1;
        // prefetch next tile into nxt buffer (safe: synced after previous compute)
        if (jt + 1 < JT_PER) {
            const int j0 = jbase + (jt + 1) * TN;
            unsigned sb = smem_u32(s_b) + (unsigned)(nxt * BUF_ELEMS) * 4u;
#pragma unroll
            for (int e = tid; e < TN * 32; e += 256) {
                int n = e >> 5, q = e & 31;
                cp16(sb + (unsigned)(n * BSTRIDE + q * 4) * 4u, &X[(j0 + n) * D_SZ + q * 4]);
            }
            if (tid < TN) {
                int t = is64 ? (int)((const long long*)targets)[j0 + tid]
                             : ((const int*)targets)[j0 + tid];
                s_sjt[nxt][tid] = make_uint2(__float_as_uint(g_sq[j0 + tid]), (unsigned)t);
            }
            CP_COMMIT();
            CP_WAIT1();   // tile `cur` complete
        } else {
            CP_WAIT0();
        }
        __syncthreads();

        // ---- 32x64 warp-tile MMA over K=128 ----
        float d[2][8][4];
#pragma unroll
        for (int mf = 0; mf < 2; mf++)
#pragma unroll
            for (int nf = 0; nf < 8; nf++)
#pragma unroll
                for (int r = 0; r < 4; r++) d[mf][nf][r] = 0.0f;

        const float* bb = s_b + cur * BUF_ELEMS + (warp_n + (lane >> 2)) * BSTRIDE + (lane & 3);
#pragma unroll
        for (int s = 0; s < 16; s++) {
            unsigned bf[8][2];
#pragma unroll
            for (int nf = 0; nf < 8; nf++) {
                bf[nf][0] = __float_as_uint(bb[nf * 8 * BSTRIDE + s * 8]);
                bf[nf][1] = __float_as_uint(bb[nf * 8 * BSTRIDE + s * 8 + 4]);
            }
#pragma unroll
            for (int mf = 0; mf < 2; mf++)
#pragma unroll
                for (int nf = 0; nf < 8; nf++)
                    mma_tf32(d[mf][nf], a_[s][mf], bf[nf][0], bf[nf][1]);
        }

        // ---- fused epilogue: v = sq_j - 2*dot, class-split min/max ----
#pragma unroll
        for (int nf = 0; nf < 8; nf++) {
            int colp = warp_n + nf * 8 + 2 * (lane & 3);
            uint4 p = *reinterpret_cast<const uint4*>(&s_sjt[cur][colp]);
            float sq0 = __uint_as_float(p.x); int t0 = (int)p.y;
            float sq1 = __uint_as_float(p.z); int t1 = (int)p.w;
#pragma unroll
            for (int mf = 0; mf < 2; mf++) {
                float v00 = fmaf(-2.0f, d[mf][nf][0], sq0);
                float v01 = fmaf(-2.0f, d[mf][nf][1], sq1);
                float v10 = fmaf(-2.0f, d[mf][nf][2], sq0);
                float v11 = fmaf(-2.0f, d[mf][nf][3], sq1);
                int s0 = 2 * mf, s1 = 2 * mf + 1;
                if (t0 == ta2[mf][0]) runm[s0] = fmaxf(runm[s0], v00);
                else                  runn[s0] = fminf(runn[s0], v00);
                if (t1 == ta2[mf][0]) runm[s0] = fmaxf(runm[s0], v01);
                else                  runn[s0] = fminf(runn[s0], v01);
                if (t0 == ta2[mf][1]) runm[s1] = fmaxf(runm[s1], v10);
                else                  runn[s1] = fminf(runn[s1], v10);
                if (t1 == ta2[mf][1]) runm[s1] = fmaxf(runm[s1], v11);
                else                  runn[s1] = fminf(runn[s1], v11);
            }
        }
        __syncthreads();   // all reads of buffer `cur` done before it is refilled
    }

    // ---- reduce across the 4 lanes sharing each row, then across warp-cols ----
#pragma unroll
    for (int slot = 0; slot < 4; slot++) {
        float m = runm[slot], n = runn[slot];
        m = fmaxf(m, __shfl_xor_sync(0xffffffffu, m, 1));
        m = fmaxf(m, __shfl_xor_sync(0xffffffffu, m, 2));
        n = fminf(n, __shfl_xor_sync(0xffffffffu, n, 1));
        n = fminf(n, __shfl_xor_sync(0xffffffffu, n, 2));
        if ((lane & 3) == 0) {
            int r = warp_m + (slot >> 1) * 16 + (lane >> 2) + 8 * (slot & 1);
            s_redm[wcol][r] = m;
            s_redn[wcol][r] = n;
        }
    }
    __syncthreads();
    if (tid < TM) {
        g_pm[half * B_SZ + i0 + tid] = fmaxf(s_redm[0][tid], s_redm[1][tid]);
        g_pn[half * B_SZ + i0 + tid] = fminf(s_redn[0][tid], s_redn[1][tid]);
    }
}

// ---------- K3a: combine splits, sqrt/relu, partial sums ----------
__global__ void fin1_kernel() {
    __shared__ double rt[512], rc[512];
    int tid = threadIdx.x;
    int a = blockIdx.x * 512 + tid;
    float m = fmaxf(g_pm[a], g_pm[B_SZ + a]);
    float n = fminf(g_pn[a], g_pn[B_SZ + a]);
    float sqi = g_sq[a];
    float dap = sqrtf(fmaxf(sqi + m, 1e-12f));
    float dan = sqrtf(fmaxf(sqi + n, 1e-12f));
    rt[tid] = (double)fmaxf(dap - dan + 0.3f, 0.0f);
    rc[tid] = (double)g_ce[a];
    __syncthreads();
    for (int s = 256; s; s >>= 1) {
        if (tid < s) { rt[tid] += rt[tid + s]; rc[tid] += rc[tid + s]; }
        __syncthreads();
    }
    if (tid == 0) { g_part_tr[blockIdx.x] = rt[0]; g_part_ce[blockIdx.x] = rc[0]; }
}

// ---------- K3b: Lambert-W + final scalar ----------
__global__ void fin2_kernel(float* __restrict__ out) {
    int lane = threadIdx.x;
    double st = (lane < 16) ? g_part_tr[lane] : 0.0;
    double sc = (lane < 16) ? g_part_ce[lane] : 0.0;
#pragma unroll
    for (int o = 16; o; o >>= 1) {
        st += __shfl_down_sync(0xffffffffu, st, o);
        sc += __shfl_down_sync(0xffffffffu, sc, o);
    }
    if (lane == 0) {
        const double LAM = 0.25;
        const double TAU = log(128.0);
        double ce = sc / (double)B_SZ;
        double l  = st / (double)B_SZ;
        double e1 = exp(1.0);
        double z = 0.5 * fmax(-2.0 / e1, (l - TAU) / LAM);
        double pv = sqrt(fmax(2.0 * (e1 * z + 1.0), 0.0));
        double wn = -1.0 + pv - pv * pv / 3.0 + (11.0 / 72.0) * pv * pv * pv;
        double w = (z < 0.0) ? wn : log1p(fmax(z, 0.0));
#pragma unroll
        for (int it = 0; it < 10; it++) {
            double ew = exp(w);
            double f = w * ew - z;
            double wp1 = w + 1.0;
            w = w - f / (ew * wp1 - (w + 2.0) * f / (2.0 * wp1));
        }
        double sigma = exp(-w);
        double ls = log(sigma);
        double loss = (ce - TAU) * sigma + LAM * ls * ls;
        out[0] = (float)(loss / (double)B_SZ);
    }
}

extern "C" void kernel_launch(void* const* d_in, const int* in_sizes, int n_in,
                              void* d_out, int out_size) {
    const float* logits = (const float*)d_in[0];
    const void* targets = d_in[1];
    float* out = (float*)d_out;
    (void)in_sizes; (void)n_in; (void)out_size;

    const int smem_bytes = 2 * BUF_ELEMS * (int)sizeof(float);   // 135168
    cudaFuncSetAttribute(triplet_mma_kernel, cudaFuncAttributeMaxDynamicSharedMemorySize,
                         smem_bytes);

    detect_kernel<<<1, 256>>>((const int*)targets);
    rowstats_kernel<<<B_SZ / 8, 256>>>(logits, targets);
    triplet_mma_kernel<<<(B_SZ / TM) * NSPLIT, 256, smem_bytes>>>(logits, targets);
    fin1_kernel<<<16, 512>>>();
    fin2_kernel<<<1, 32>>>(out);
}

// round 4
// speedup vs baseline: 6.4113x; 1.3864x over previous
#include <cuda_runtime.h>
#include <cuda_fp16.h>
#include <math.h>
#include <stdint.h>

#define B_SZ 8192
#define D_SZ 128
#define TM 128          // anchors per CTA
#define TN 128          // j-cols per tile
#define NSPLIT 2
#define JT_PER (B_SZ / NSPLIT / TN)   // 32 tiles
#define BSTRIDE_H 136   // padded B smem row stride (halfs): banks (4g+t)%32 -> conflict-free
#define BUF_H (TN * BSTRIDE_H)

__device__ __half g_xh[B_SZ * D_SZ];   // fp16 copy of logits (written by rowstats)
__device__ float  g_sq[B_SZ];
__device__ float  g_ce[B_SZ];
__device__ float  g_pm[NSPLIT * B_SZ];
__device__ float  g_pn[NSPLIT * B_SZ];
__device__ int    g_is64;

// ---------------- PTX helpers (baseline ISA only) ----------------
__device__ __forceinline__ void mma_f16(float d[4], const unsigned a[4],
                                        unsigned b0, unsigned b1) {
    asm volatile(
        "mma.sync.aligned.m16n8k16.row.col.f32.f16.f16.f32 "
        "{%0,%1,%2,%3}, {%4,%5,%6,%7}, {%8,%9}, {%0,%1,%2,%3};"
        : "+f"(d[0]), "+f"(d[1]), "+f"(d[2]), "+f"(d[3])
        : "r"(a[0]), "r"(a[1]), "r"(a[2]), "r"(a[3]), "r"(b0), "r"(b1));
}
__device__ __forceinline__ unsigned smem_u32(const void* p) {
    unsigned a;
    asm("{ .reg .u64 t; cvta.to.shared.u64 t, %1; cvt.u32.u64 %0, t; }" : "=r"(a) : "l"(p));
    return a;
}
__device__ __forceinline__ void cp16(unsigned dst, const void* src) {
    asm volatile("cp.async.cg.shared.global [%0], [%1], 16;" :: "r"(dst), "l"(src) : "memory");
}
#define CP_COMMIT() asm volatile("cp.async.commit_group;" ::: "memory")
#define CP_WAIT1()  asm volatile("cp.async.wait_group 1;" ::: "memory")
#define CP_WAIT0()  asm volatile("cp.async.wait_group 0;" ::: "memory")

// ---------- K0: detect int64 vs int32 targets ----------
__global__ void detect_kernel(const int* __restrict__ t32) {
    __shared__ int sred[256];
    int tid = threadIdx.x;
    int v = 0;
    for (int i = tid; i < B_SZ / 2; i += 256) v |= t32[2 * i + 1];
    sred[tid] = v;
    __syncthreads();
    for (int s = 128; s; s >>= 1) {
        if (tid < s) sred[tid] |= sred[tid + s];
        __syncthreads();
    }
    if (tid == 0) g_is64 = (sred[0] == 0) ? 1 : 0;
}

// ---------- K1: sum-of-squares + CE + fp16 copy of X ----------
__global__ void rowstats_kernel(const float* __restrict__ logits, const void* __restrict__ targets) {
    int lane = threadIdx.x & 31;
    int row = (blockIdx.x << 3) + (threadIdx.x >> 5);
    float4 v = reinterpret_cast<const float4*>(logits)[row * 32 + lane];
    // fp16 copy (round-to-nearest)
    {
        __half2 h0 = __floats2half2_rn(v.x, v.y);
        __half2 h1 = __floats2half2_rn(v.z, v.w);
        unsigned u0, u1;
        u0 = *reinterpret_cast<unsigned*>(&h0);
        u1 = *reinterpret_cast<unsigned*>(&h1);
        reinterpret_cast<uint2*>(g_xh)[row * 32 + lane] = make_uint2(u0, u1);
    }
    float ss = fmaf(v.x, v.x, fmaf(v.y, v.y, fmaf(v.z, v.z, v.w * v.w)));
    float mx = fmaxf(fmaxf(v.x, v.y), fmaxf(v.z, v.w));
#pragma unroll
    for (int o = 16; o; o >>= 1) {
        ss += __shfl_xor_sync(0xffffffffu, ss, o);
        mx = fmaxf(mx, __shfl_xor_sync(0xffffffffu, mx, o));
    }
    float se = expf(v.x - mx) + expf(v.y - mx) + expf(v.z - mx) + expf(v.w - mx);
#pragma unroll
    for (int o = 16; o; o >>= 1) se += __shfl_xor_sync(0xffffffffu, se, o);
    int t = g_is64 ? (int)((const long long*)targets)[row] : ((const int*)targets)[row];
    int c = t & 3;
    float tv = (c == 0) ? v.x : (c == 1) ? v.y : (c == 2) ? v.z : v.w;
    tv = __shfl_sync(0xffffffffu, tv, t >> 2);
    if (lane == 0) {
        g_sq[row] = ss;
        g_ce[row] = mx + logf(se) - tv;
    }
}

// ---------- K2: mma.sync fp16 Gram + fused batch-hard mining ----------
// 128 CTAs: strip = bx>>1 (128 anchors), half = bx&1 (4096 cols, 32 tiles).
// 8 warps: warp_m=(wid&3)*32 rows, warp_n=(wid>>2)*64 cols. A in registers (fp16).
extern __shared__ __half s_b[];   // [2][TN][BSTRIDE_H]

__global__ void __launch_bounds__(256, 1)
triplet_mma_kernel(const void* __restrict__ targets) {
    __shared__ __align__(16) uint2 s_sjt[2][TN];   // {sq bits, target}
    __shared__ int   s_ta[TM];
    __shared__ float s_redm[2][TM], s_redn[2][TM];

    const int tid  = threadIdx.x;
    const int wid  = tid >> 5;
    const int lane = tid & 31;
    const int warp_m = (wid & 3) * 32;
    const int wcol   = wid >> 2;
    const int warp_n = wcol * 64;
    const int strip = blockIdx.x >> 1;
    const int half  = blockIdx.x & 1;
    const int i0    = strip * TM;
    const int jbase = half * (B_SZ / NSPLIT);
    const int is64  = g_is64;

    // ---- prefetch tile 0 ----
    {
        const int j0 = jbase;
        unsigned sb = smem_u32(s_b);
#pragma unroll
        for (int e = tid; e < TN * 16; e += 256) {
            int n = e >> 4, q = e & 15;
            cp16(sb + (unsigned)(n * BSTRIDE_H + q * 8) * 2u, &g_xh[(j0 + n) * D_SZ + q * 8]);
        }
        if (tid < TN) {
            int t = is64 ? (int)((const long long*)targets)[j0 + tid]
                         : ((const int*)targets)[j0 + tid];
            s_sjt[0][tid] = make_uint2(__float_as_uint(g_sq[j0 + tid]), (unsigned)t);
        }
        CP_COMMIT();
    }
    if (tid < TM)
        s_ta[tid] = is64 ? (int)((const long long*)targets)[i0 + tid]
                         : ((const int*)targets)[i0 + tid];

    // ---- A fragments in registers (fp16), fixed across all tiles ----
    // a0={A[g][2t,2t+1]}, a1={A[g+8][..]}, a2={A[g][2t+8..]}, a3={A[g+8][2t+8..]}
    unsigned a_[8][2][4];
    {
        const unsigned* Xu = reinterpret_cast<const unsigned*>(g_xh);
        const int g = lane >> 2, t = lane & 3;
#pragma unroll
        for (int s = 0; s < 8; s++) {
#pragma unroll
            for (int mf = 0; mf < 2; mf++) {
                int r = i0 + warp_m + mf * 16 + g;
                int k2 = s * 8 + t;   // half2 index: k = s*16 + t*2
                a_[s][mf][0] = __ldg(&Xu[r * 64 + k2]);
                a_[s][mf][1] = __ldg(&Xu[(r + 8) * 64 + k2]);
                a_[s][mf][2] = __ldg(&Xu[r * 64 + k2 + 4]);
                a_[s][mf][3] = __ldg(&Xu[(r + 8) * 64 + k2 + 4]);
            }
        }
    }

    __syncthreads();   // s_ta visible
    int ta2[2][2];
#pragma unroll
    for (int mf = 0; mf < 2; mf++)
#pragma unroll
        for (int h = 0; h < 2; h++)
            ta2[mf][h] = s_ta[warp_m + mf * 16 + (lane >> 2) + 8 * h];

    float runm[4], runn[4];
#pragma unroll
    for (int s = 0; s < 4; s++) { runm[s] = -INFINITY; runn[s] = INFINITY; }

    for (int jt = 0; jt < JT_PER; jt++) {
        const int cur = jt & 1, nxt = cur ^ 1;
        if (jt + 1 < JT_PER) {
            const int j0 = jbase + (jt + 1) * TN;
            unsigned sb = smem_u32(s_b) + (unsigned)(nxt * BUF_H) * 2u;
#pragma unroll
            for (int e = tid; e < TN * 16; e += 256) {
                int n = e >> 4, q = e & 15;
                cp16(sb + (unsigned)(n * BSTRIDE_H + q * 8) * 2u,
                     &g_xh[(j0 + n) * D_SZ + q * 8]);
            }
            if (tid < TN) {
                int t = is64 ? (int)((const long long*)targets)[j0 + tid]
                             : ((const int*)targets)[j0 + tid];
                s_sjt[nxt][tid] = make_uint2(__float_as_uint(g_sq[j0 + tid]), (unsigned)t);
            }
            CP_COMMIT();
            CP_WAIT1();
        } else {
            CP_WAIT0();
        }
        __syncthreads();

        // ---- 32x64 warp-tile MMA over K=128 (8 k16 steps) ----
        float d[2][8][4];
#pragma unroll
        for (int mf = 0; mf < 2; mf++)
#pragma unroll
            for (int nf = 0; nf < 8; nf++)
#pragma unroll
                for (int r = 0; r < 4; r++) d[mf][nf][r] = 0.0f;

        // B frags: b0 = {B[k=2t][c]}, b1 = {B[k=2t+8][c]}, c = g (n index)
        const __half* bb = s_b + cur * BUF_H + (warp_n + (lane >> 2)) * BSTRIDE_H + (lane & 3) * 2;
#pragma unroll
        for (int s = 0; s < 8; s++) {
            unsigned bf[8][2];
#pragma unroll
            for (int nf = 0; nf < 8; nf++) {
                bf[nf][0] = *reinterpret_cast<const unsigned*>(bb + nf * 8 * BSTRIDE_H + s * 16);
                bf[nf][1] = *reinterpret_cast<const unsigned*>(bb + nf * 8 * BSTRIDE_H + s * 16 + 8);
            }
#pragma unroll
            for (int mf = 0; mf < 2; mf++)
#pragma unroll
                for (int nf = 0; nf < 8; nf++)
                    mma_f16(d[mf][nf], a_[s][mf], bf[nf][0], bf[nf][1]);
        }

        // ---- fused epilogue: v = sq_j - 2*dot, class-split min/max ----
#pragma unroll
        for (int nf = 0; nf < 8; nf++) {
            int colp = warp_n + nf * 8 + 2 * (lane & 3);
            uint4 p = *reinterpret_cast<const uint4*>(&s_sjt[cur][colp]);
            float sq0 = __uint_as_float(p.x); int t0 = (int)p.y;
            float sq1 = __uint_as_float(p.z); int t1 = (int)p.w;
#pragma unroll
            for (int mf = 0; mf < 2; mf++) {
                float v00 = fmaf(-2.0f, d[mf][nf][0], sq0);
                float v01 = fmaf(-2.0f, d[mf][nf][1], sq1);
                float v10 = fmaf(-2.0f, d[mf][nf][2], sq0);
                float v11 = fmaf(-2.0f, d[mf][nf][3], sq1);
                int s0 = 2 * mf, s1 = 2 * mf + 1;
                if (t0 == ta2[mf][0]) runm[s0] = fmaxf(runm[s0], v00);
                else                  runn[s0] = fminf(runn[s0], v00);
                if (t1 == ta2[mf][0]) runm[s0] = fmaxf(runm[s0], v01);
                else                  runn[s0] = fminf(runn[s0], v01);
                if (t0 == ta2[mf][1]) runm[s1] = fmaxf(runm[s1], v10);
                else                  runn[s1] = fminf(runn[s1], v10);
                if (t1 == ta2[mf][1]) runm[s1] = fmaxf(runm[s1], v11);
                else                  runn[s1] = fminf(runn[s1], v11);
            }
        }
        __syncthreads();
    }

    // ---- reduce across 4 lanes sharing each row, then across warp-cols ----
#pragma unroll
    for (int slot = 0; slot < 4; slot++) {
        float m = runm[slot], n = runn[slot];
        m = fmaxf(m, __shfl_xor_sync(0xffffffffu, m, 1));
        m = fmaxf(m, __shfl_xor_sync(0xffffffffu, m, 2));
        n = fminf(n, __shfl_xor_sync(0xffffffffu, n, 1));
        n = fminf(n, __shfl_xor_sync(0xffffffffu, n, 2));
        if ((lane & 3) == 0) {
            int r = warp_m + (slot >> 1) * 16 + (lane >> 2) + 8 * (slot & 1);
            s_redm[wcol][r] = m;
            s_redn[wcol][r] = n;
        }
    }
    __syncthreads();
    if (tid < TM) {
        g_pm[half * B_SZ + i0 + tid] = fmaxf(s_redm[0][tid], s_redm[1][tid]);
        g_pn[half * B_SZ + i0 + tid] = fminf(s_redn[0][tid], s_redn[1][tid]);
    }
}

// ---------- K3: fused reduction + Lambert-W + final scalar ----------
__global__ void fin_kernel(float* __restrict__ out) {
    __shared__ double rt[1024], rc[1024];
    int tid = threadIdx.x;
    double st = 0.0, sc = 0.0;
#pragma unroll
    for (int a = tid; a < B_SZ; a += 1024) {
        float m = fmaxf(g_pm[a], g_pm[B_SZ + a]);
        float n = fminf(g_pn[a], g_pn[B_SZ + a]);
        float sqi = g_sq[a];
        float dap = sqrtf(fmaxf(sqi + m, 1e-12f));
        float dan = sqrtf(fmaxf(sqi + n, 1e-12f));
        st += (double)fmaxf(dap - dan + 0.3f, 0.0f);
        sc += (double)g_ce[a];
    }
    rt[tid] = st; rc[tid] = sc;
    __syncthreads();
    for (int s = 512; s; s >>= 1) {
        if (tid < s) { rt[tid] += rt[tid + s]; rc[tid] += rc[tid + s]; }
        __syncthreads();
    }
    if (tid == 0) {
        const double LAM = 0.25;
        const double TAU = log(128.0);
        double ce = rc[0] / (double)B_SZ;
        double l  = rt[0] / (double)B_SZ;
        double e1 = exp(1.0);
        double z = 0.5 * fmax(-2.0 / e1, (l - TAU) / LAM);
        double pv = sqrt(fmax(2.0 * (e1 * z + 1.0), 0.0));
        double wn = -1.0 + pv - pv * pv / 3.0 + (11.0 / 72.0) * pv * pv * pv;
        double w = (z < 0.0) ? wn : log1p(fmax(z, 0.0));
#pragma unroll
        for (int it = 0; it < 10; it++) {
            double ew = exp(w);
            double f = w * ew - z;
            double wp1 = w + 1.0;
            w = w - f / (ew * wp1 - (w + 2.0) * f / (2.0 * wp1));
        }
        double sigma = exp(-w);
        double ls = log(sigma);
        double loss = (ce - TAU) * sigma + LAM * ls * ls;
        out[0] = (float)(loss / (double)B_SZ);
    }
}

extern "C" void kernel_launch(void* const* d_in, const int* in_sizes, int n_in,
                              void* d_out, int out_size) {
    const float* logits = (const float*)d_in[0];
    const void* targets = d_in[1];
    float* out = (float*)d_out;
    (void)in_sizes; (void)n_in; (void)out_size;

    const int smem_bytes = 2 * BUF_H * (int)sizeof(__half);   // 69632
    cudaFuncSetAttribute(triplet_mma_kernel, cudaFuncAttributeMaxDynamicSharedMemorySize,
                         smem_bytes);

    detect_kernel<<<1, 256>>>((const int*)targets);
    rowstats_kernel<<<B_SZ / 8, 256>>>(logits, targets);
    triplet_mma_kernel<<<(B_SZ / TM) * NSPLIT, 256, smem_bytes>>>(targets);
    fin_kernel<<<1, 1024>>>(out);
}

// round 5
// speedup vs baseline: 6.7776x; 1.0571x over previous
#include <cuda_runtime.h>
#include <cuda_fp16.h>
#include <math.h>
#include <stdint.h>

#define B_SZ 8192
#define D_SZ 128
#define TM 128
#define TN 128
#define S_STRIPS (B_SZ / TM)             // 64
#define TILES_TOT (S_STRIPS * (S_STRIPS + 1) / 2)   // 2080
#define NCTA 130
#define TPC (TILES_TOT / NCTA)           // 16
#define BSTRIDE_H 136                    // padded smem row stride (halfs), conflict-free
#define BUF_H (TN * BSTRIDE_H)

__device__ __half   g_xh[B_SZ * D_SZ];
__device__ float    g_sq[B_SZ];
__device__ float    g_ce[B_SZ];
__device__ unsigned g_pm[B_SZ];          // order-encoded float max (pos candidates)
__device__ unsigned g_pn[B_SZ];          // order-encoded float min (neg candidates)
__device__ int      g_is64;

// ---------------- helpers ----------------
__device__ __forceinline__ unsigned encf(float f) {
    unsigned u = __float_as_uint(f);
    return ((int)u < 0) ? ~u : (u | 0x80000000u);
}
__device__ __forceinline__ float decf(unsigned u) {
    return (u & 0x80000000u) ? __uint_as_float(u & 0x7fffffffu) : __uint_as_float(~u);
}
__device__ __forceinline__ void mma_f16(float d[4], const unsigned a[4],
                                        unsigned b0, unsigned b1) {
    asm volatile(
        "mma.sync.aligned.m16n8k16.row.col.f32.f16.f16.f32 "
        "{%0,%1,%2,%3}, {%4,%5,%6,%7}, {%8,%9}, {%0,%1,%2,%3};"
        : "+f"(d[0]), "+f"(d[1]), "+f"(d[2]), "+f"(d[3])
        : "r"(a[0]), "r"(a[1]), "r"(a[2]), "r"(a[3]), "r"(b0), "r"(b1));
}
__device__ __forceinline__ unsigned smem_u32(const void* p) {
    unsigned a;
    asm("{ .reg .u64 t; cvta.to.shared.u64 t, %1; cvt.u32.u64 %0, t; }" : "=r"(a) : "l"(p));
    return a;
}
__device__ __forceinline__ void cp16(unsigned dst, const void* src) {
    asm volatile("cp.async.cg.shared.global [%0], [%1], 16;" :: "r"(dst), "l"(src) : "memory");
}
#define CP_COMMIT() asm volatile("cp.async.commit_group;" ::: "memory")
#define CP_WAIT1()  asm volatile("cp.async.wait_group 1;" ::: "memory")
#define CP_WAIT0()  asm volatile("cp.async.wait_group 0;" ::: "memory")

// ---------- K0: detect int64 vs int32 targets ----------
__global__ void detect_kernel(const int* __restrict__ t32) {
    __shared__ int sred[256];
    int tid = threadIdx.x;
    int v = 0;
    for (int i = tid; i < B_SZ / 2; i += 256) v |= t32[2 * i + 1];
    sred[tid] = v;
    __syncthreads();
    for (int s = 128; s; s >>= 1) {
        if (tid < s) sred[tid] |= sred[tid + s];
        __syncthreads();
    }
    if (tid == 0) g_is64 = (sred[0] == 0) ? 1 : 0;
}

// ---------- K1: sum-of-squares + CE + fp16 copy + minmax init ----------
__global__ void rowstats_kernel(const float* __restrict__ logits, const void* __restrict__ targets) {
    int lane = threadIdx.x & 31;
    int row = (blockIdx.x << 3) + (threadIdx.x >> 5);
    float4 v = reinterpret_cast<const float4*>(logits)[row * 32 + lane];
    {
        __half2 h0 = __floats2half2_rn(v.x, v.y);
        __half2 h1 = __floats2half2_rn(v.z, v.w);
        reinterpret_cast<uint2*>(g_xh)[row * 32 + lane] =
            make_uint2(*reinterpret_cast<unsigned*>(&h0), *reinterpret_cast<unsigned*>(&h1));
    }
    float ss = fmaf(v.x, v.x, fmaf(v.y, v.y, fmaf(v.z, v.z, v.w * v.w)));
    float mx = fmaxf(fmaxf(v.x, v.y), fmaxf(v.z, v.w));
#pragma unroll
    for (int o = 16; o; o >>= 1) {
        ss += __shfl_xor_sync(0xffffffffu, ss, o);
        mx = fmaxf(mx, __shfl_xor_sync(0xffffffffu, mx, o));
    }
    float se = expf(v.x - mx) + expf(v.y - mx) + expf(v.z - mx) + expf(v.w - mx);
#pragma unroll
    for (int o = 16; o; o >>= 1) se += __shfl_xor_sync(0xffffffffu, se, o);
    int t = g_is64 ? (int)((const long long*)targets)[row] : ((const int*)targets)[row];
    int c = t & 3;
    float tv = (c == 0) ? v.x : (c == 1) ? v.y : (c == 2) ? v.z : v.w;
    tv = __shfl_sync(0xffffffffu, tv, t >> 2);
    if (lane == 0) {
        g_sq[row] = ss;
        g_ce[row] = mx + logf(se) - tv;
        g_pm[row] = 0u;             // encode-min
        g_pn[row] = 0xFFFFFFFFu;    // encode-max
    }
}

// ---------- K2: symmetric fp16 MMA Gram + two-sided batch-hard mining ----------
// 130 CTAs x 16 upper-triangular tiles each. 8 warps: warp (wrow=wid&3, wcol=wid>>2),
// warp tile 32x64. A strip in smem (reloaded on tile-row change), B double-buffered.
extern __shared__ __half s_all[];   // A: [0,BUF_H) ; B0: [BUF_H,2BUF_H) ; B1: [2BUF_H,3BUF_H)

__global__ void __launch_bounds__(256, 1)
triplet_mma_kernel(const void* __restrict__ targets) {
    __shared__ __align__(16) uint2 s_sjt[2][TN];   // {sq_j bits, t_j}
    __shared__ int   s_ta[TM];
    __shared__ float s_sqa[TM];

    const int tid  = threadIdx.x;
    const int lane = tid & 31;
    const int wid  = tid >> 5;
    const int warp_m = (wid & 3) * 32;
    const int warp_n = (wid >> 2) * 64;
    const int g = lane >> 2, tq = lane & 3;
    const int is64 = g_is64;

    // ---- first tile (i,j) of this CTA ----
    int T0 = blockIdx.x * TPC;
    int ti = 0, rem = T0;
    while (rem >= S_STRIPS - ti) { rem -= S_STRIPS - ti; ti++; }
    int tj = ti + rem;

    __half* s_a = s_all;

    // load A strip (plain loads), s_ta, s_sqa
    {
        const uint4* Xu = reinterpret_cast<const uint4*>(g_xh);
        for (int e = tid; e < TM * 16; e += 256) {
            int n = e >> 4, q = e & 15;
            *reinterpret_cast<uint4*>(&s_a[n * BSTRIDE_H + q * 8]) = Xu[(ti * TM + n) * 16 + q];
        }
        if (tid < TM) {
            int r = ti * TM + tid;
            s_ta[tid] = is64 ? (int)((const long long*)targets)[r] : ((const int*)targets)[r];
            s_sqa[tid] = g_sq[r];
        }
    }
    // prefetch B tile 0
    {
        int j0 = tj * TN;
        unsigned sb = smem_u32(s_all) + (unsigned)BUF_H * 2u;
        for (int e = tid; e < TN * 16; e += 256) {
            int n = e >> 4, q = e & 15;
            cp16(sb + (unsigned)(n * BSTRIDE_H + q * 8) * 2u, &g_xh[(j0 + n) * D_SZ + q * 8]);
        }
        if (tid < TN) {
            int t = is64 ? (int)((const long long*)targets)[j0 + tid]
                         : ((const int*)targets)[j0 + tid];
            s_sjt[0][tid] = make_uint2(__float_as_uint(g_sq[j0 + tid]), (unsigned)t);
        }
        CP_COMMIT();
    }
    __syncthreads();

    int ta2[2][2];
    float sqa4[4];
    int reg_i = ti;
#pragma unroll
    for (int mf = 0; mf < 2; mf++)
#pragma unroll
        for (int h = 0; h < 2; h++) {
            int r = warp_m + mf * 16 + g + 8 * h;
            ta2[mf][h] = s_ta[r];
            sqa4[2 * mf + h] = s_sqa[r];
        }

    float runm[4], runn[4];
#pragma unroll
    for (int s = 0; s < 4; s++) { runm[s] = -INFINITY; runn[s] = INFINITY; }

    for (int t = 0; t < TPC; t++) {
        const int cur = t & 1, nxt = cur ^ 1;
        // next tile coords
        int ni = ti, nj = tj + 1;
        if (nj == S_STRIPS) { ni = ti + 1; nj = ni; }
        const bool last = (t == TPC - 1);
        const bool rowchg = (!last) && (ni != ti);

        // reload regs if strip changed at previous boundary (smem synced already)
        if (reg_i != ti) {
            reg_i = ti;
#pragma unroll
            for (int mf = 0; mf < 2; mf++)
#pragma unroll
                for (int h = 0; h < 2; h++) {
                    int r = warp_m + mf * 16 + g + 8 * h;
                    ta2[mf][h] = s_ta[r];
                    sqa4[2 * mf + h] = s_sqa[r];
                }
        }

        // prefetch next B
        if (!last) {
            int j0 = nj * TN;
            unsigned sb = smem_u32(s_all) + (unsigned)(BUF_H * (1 + nxt)) * 2u;
            for (int e = tid; e < TN * 16; e += 256) {
                int n = e >> 4, q = e & 15;
                cp16(sb + (unsigned)(n * BSTRIDE_H + q * 8) * 2u, &g_xh[(j0 + n) * D_SZ + q * 8]);
            }
            if (tid < TN) {
                int tt = is64 ? (int)((const long long*)targets)[j0 + tid]
                              : ((const int*)targets)[j0 + tid];
                s_sjt[nxt][tid] = make_uint2(__float_as_uint(g_sq[j0 + tid]), (unsigned)tt);
            }
            CP_COMMIT();
            CP_WAIT1();
        } else {
            CP_WAIT0();
        }
        __syncthreads();

        // ---- MMA 32x64 over K=128 ----
        float d[2][8][4];
#pragma unroll
        for (int mf = 0; mf < 2; mf++)
#pragma unroll
            for (int nf = 0; nf < 8; nf++)
#pragma unroll
                for (int r = 0; r < 4; r++) d[mf][nf][r] = 0.0f;

        const __half* pa = s_a + (warp_m + g) * BSTRIDE_H + tq * 2;
        const __half* bb = s_all + BUF_H * (1 + cur) + (warp_n + g) * BSTRIDE_H + tq * 2;
#pragma unroll
        for (int s = 0; s < 8; s++) {
            unsigned af[2][4];
#pragma unroll
            for (int mf = 0; mf < 2; mf++) {
                const __half* p = pa + mf * 16 * BSTRIDE_H + s * 16;
                af[mf][0] = *reinterpret_cast<const unsigned*>(p);
                af[mf][1] = *reinterpret_cast<const unsigned*>(p + 8 * BSTRIDE_H);
                af[mf][2] = *reinterpret_cast<const unsigned*>(p + 8);
                af[mf][3] = *reinterpret_cast<const unsigned*>(p + 8 * BSTRIDE_H + 8);
            }
            unsigned bf[8][2];
#pragma unroll
            for (int nf = 0; nf < 8; nf++) {
                bf[nf][0] = *reinterpret_cast<const unsigned*>(bb + nf * 8 * BSTRIDE_H + s * 16);
                bf[nf][1] = *reinterpret_cast<const unsigned*>(bb + nf * 8 * BSTRIDE_H + s * 16 + 8);
            }
#pragma unroll
            for (int mf = 0; mf < 2; mf++)
#pragma unroll
                for (int nf = 0; nf < 8; nf++)
                    mma_f16(d[mf][nf], af[mf], bf[nf][0], bf[nf][1]);
        }

        // ---- two-sided epilogue ----
        float colm[8][2], coln[8][2];
#pragma unroll
        for (int nf = 0; nf < 8; nf++)
#pragma unroll
            for (int p = 0; p < 2; p++) { colm[nf][p] = -INFINITY; coln[nf][p] = INFINITY; }

#pragma unroll
        for (int nf = 0; nf < 8; nf++) {
            int colp = warp_n + nf * 8 + 2 * tq;
            uint4 pjt = *reinterpret_cast<const uint4*>(&s_sjt[cur][colp]);
            float sq0 = __uint_as_float(pjt.x); int t0 = (int)pjt.y;
            float sq1 = __uint_as_float(pjt.z); int t1 = (int)pjt.w;
#pragma unroll
            for (int mf = 0; mf < 2; mf++) {
                int s0 = 2 * mf, s1 = 2 * mf + 1;
                // e0: row g, col 2tq
                {
                    float vr = fmaf(-2.0f, d[mf][nf][0], sq0);
                    float vc = fmaf(-2.0f, d[mf][nf][0], sqa4[s0]);
                    if (t0 == ta2[mf][0]) { runm[s0] = fmaxf(runm[s0], vr); colm[nf][0] = fmaxf(colm[nf][0], vc); }
                    else                  { runn[s0] = fminf(runn[s0], vr); coln[nf][0] = fminf(coln[nf][0], vc); }
                }
                // e1: row g, col 2tq+1
                {
                    float vr = fmaf(-2.0f, d[mf][nf][1], sq1);
                    float vc = fmaf(-2.0f, d[mf][nf][1], sqa4[s0]);
                    if (t1 == ta2[mf][0]) { runm[s0] = fmaxf(runm[s0], vr); colm[nf][1] = fmaxf(colm[nf][1], vc); }
                    else                  { runn[s0] = fminf(runn[s0], vr); coln[nf][1] = fminf(coln[nf][1], vc); }
                }
                // e2: row g+8, col 2tq
                {
                    float vr = fmaf(-2.0f, d[mf][nf][2], sq0);
                    float vc = fmaf(-2.0f, d[mf][nf][2], sqa4[s1]);
                    if (t0 == ta2[mf][1]) { runm[s1] = fmaxf(runm[s1], vr); colm[nf][0] = fmaxf(colm[nf][0], vc); }
                    else                  { runn[s1] = fminf(runn[s1], vr); coln[nf][0] = fminf(coln[nf][0], vc); }
                }
                // e3: row g+8, col 2tq+1
                {
                    float vr = fmaf(-2.0f, d[mf][nf][3], sq1);
                    float vc = fmaf(-2.0f, d[mf][nf][3], sqa4[s1]);
                    if (t1 == ta2[mf][1]) { runm[s1] = fmaxf(runm[s1], vr); colm[nf][1] = fmaxf(colm[nf][1], vc); }
                    else                  { runn[s1] = fminf(runn[s1], vr); coln[nf][1] = fminf(coln[nf][1], vc); }
                }
            }
        }

        // ---- col flush (every tile): reduce over g-lanes, atomics ----
        {
            const int j0 = tj * TN;
#pragma unroll
            for (int nf = 0; nf < 8; nf++)
#pragma unroll
                for (int p = 0; p < 2; p++) {
                    float m = colm[nf][p], n = coln[nf][p];
                    m = fmaxf(m, __shfl_xor_sync(0xffffffffu, m, 4));
                    m = fmaxf(m, __shfl_xor_sync(0xffffffffu, m, 8));
                    m = fmaxf(m, __shfl_xor_sync(0xffffffffu, m, 16));
                    n = fminf(n, __shfl_xor_sync(0xffffffffu, n, 4));
                    n = fminf(n, __shfl_xor_sync(0xffffffffu, n, 8));
                    n = fminf(n, __shfl_xor_sync(0xffffffffu, n, 16));
                    if (lane < 4) {
                        int gc = j0 + warp_n + nf * 8 + 2 * lane + p;
                        atomicMax(&g_pm[gc], encf(m));
                        atomicMin(&g_pn[gc], encf(n));
                    }
                }
        }

        // ---- row flush on strip change / end ----
        if (last || rowchg) {
            const int i0 = ti * TM;
#pragma unroll
            for (int slot = 0; slot < 4; slot++) {
                float m = runm[slot], n = runn[slot];
                m = fmaxf(m, __shfl_xor_sync(0xffffffffu, m, 1));
                m = fmaxf(m, __shfl_xor_sync(0xffffffffu, m, 2));
                n = fminf(n, __shfl_xor_sync(0xffffffffu, n, 1));
                n = fminf(n, __shfl_xor_sync(0xffffffffu, n, 2));
                if (tq == 0) {
                    int r = i0 + warp_m + (slot >> 1) * 16 + g + 8 * (slot & 1);
                    atomicMax(&g_pm[r], encf(m));
                    atomicMin(&g_pn[r], encf(n));
                }
                runm[slot] = -INFINITY; runn[slot] = INFINITY;
            }
        }
        // ---- reload A strip if next tile is a new row ----
        if (rowchg) {
            __syncthreads();   // everyone done reading s_a / s_ta for this strip
            const uint4* Xu = reinterpret_cast<const uint4*>(g_xh);
            for (int e = tid; e < TM * 16; e += 256) {
                int n = e >> 4, q = e & 15;
                *reinterpret_cast<uint4*>(&s_a[n * BSTRIDE_H + q * 8]) = Xu[(ni * TM + n) * 16 + q];
            }
            if (tid < TM) {
                int r = ni * TM + tid;
                s_ta[tid] = is64 ? (int)((const long long*)targets)[r] : ((const int*)targets)[r];
                s_sqa[tid] = g_sq[r];
            }
        }
        __syncthreads();   // protects B cur buffer reuse + new A/s_ta visibility
        ti = ni; tj = nj;
    }
}

// ---------- K3: reduction + Lambert-W + final scalar ----------
__global__ void fin_kernel(float* __restrict__ out) {
    __shared__ double s_rt[8], s_rc[8];
    int tid = threadIdx.x;
    int lane = tid & 31, wid = tid >> 5;
    double st = 0.0, sc = 0.0;
    for (int a = tid; a < B_SZ; a += 256) {
        float m = decf(g_pm[a]);
        float n = decf(g_pn[a]);
        float sqi = g_sq[a];
        float dap = sqrtf(fmaxf(sqi + m, 1e-12f));
        float dan = sqrtf(fmaxf(sqi + n, 1e-12f));
        st += (double)fmaxf(dap - dan + 0.3f, 0.0f);
        sc += (double)g_ce[a];
    }
#pragma unroll
    for (int o = 16; o; o >>= 1) {
        st += __shfl_down_sync(0xffffffffu, st, o);
        sc += __shfl_down_sync(0xffffffffu, sc, o);
    }
    if (lane == 0) { s_rt[wid] = st; s_rc[wid] = sc; }
    __syncthreads();
    if (tid == 0) {
        double T = 0.0, Cs = 0.0;
#pragma unroll
        for (int w = 0; w < 8; w++) { T += s_rt[w]; Cs += s_rc[w]; }
        const double LAM = 0.25;
        const double TAU = log(128.0);
        double ce = Cs / (double)B_SZ;
        double l  = T / (double)B_SZ;
        double e1 = exp(1.0);
        double z = 0.5 * fmax(-2.0 / e1, (l - TAU) / LAM);
        double pv = sqrt(fmax(2.0 * (e1 * z + 1.0), 0.0));
        double wn = -1.0 + pv - pv * pv / 3.0 + (11.0 / 72.0) * pv * pv * pv;
        double w = (z < 0.0) ? wn : log1p(fmax(z, 0.0));
#pragma unroll
        for (int it = 0; it < 8; it++) {
            double ew = exp(w);
            double f = w * ew - z;
            double wp1 = w + 1.0;
            w = w - f / (ew * wp1 - (w + 2.0) * f / (2.0 * wp1));
        }
        double sigma = exp(-w);
        double ls = log(sigma);
        double loss = (ce - TAU) * sigma + LAM * ls * ls;
        out[0] = (float)(loss / (double)B_SZ);
    }
}

extern "C" void kernel_launch(void* const* d_in, const int* in_sizes, int n_in,
                              void* d_out, int out_size) {
    const float* logits = (const float*)d_in[0];
    const void* targets = d_in[1];
    float* out = (float*)d_out;
    (void)in_sizes; (void)n_in; (void)out_size;

    const int smem_bytes = 3 * BUF_H * (int)sizeof(__half);   // 104448
    cudaFuncSetAttribute(triplet_mma_kernel, cudaFuncAttributeMaxDynamicSharedMemorySize,
                         smem_bytes);

    detect_kernel<<<1, 256>>>((const int*)targets);
    rowstats_kernel<<<B_SZ / 8, 256>>>(logits, targets);
    triplet_mma_kernel<<<NCTA, 256, smem_bytes>>>(targets);
    fin_kernel<<<1, 256>>>(out);
}

// round 6
// speedup vs baseline: 8.5579x; 1.2627x over previous
#include <cuda_runtime.h>
#include <cuda_fp16.h>
#include <math.h>
#include <stdint.h>

#define B_SZ 8192
#define D_SZ 128
#define TM 128
#define TN 128
#define S_STRIPS (B_SZ / TM)             // 64
#define TILES_TOT (S_STRIPS * (S_STRIPS + 1) / 2)   // 2080
#define NCTA 130
#define TPC (TILES_TOT / NCTA)           // 16
#define BSTRIDE_H 136                    // padded smem row stride (halfs), conflict-free
#define BUF_H (TN * BSTRIDE_H)

__device__ __half   g_xh[B_SZ * D_SZ];
__device__ float    g_sq[B_SZ];
__device__ float    g_ce[B_SZ];
__device__ unsigned g_pm[B_SZ];          // order-encoded float max (pos candidates)
__device__ unsigned g_pn[B_SZ];          // order-encoded float min (neg candidates)
__device__ int      g_is64;

// ---------------- helpers ----------------
__device__ __forceinline__ unsigned encf(float f) {
    unsigned u = __float_as_uint(f);
    return ((int)u < 0) ? ~u : (u | 0x80000000u);
}
__device__ __forceinline__ float decf(unsigned u) {
    return (u & 0x80000000u) ? __uint_as_float(u & 0x7fffffffu) : __uint_as_float(~u);
}
__device__ __forceinline__ void mma_f16(float d[4], const unsigned a[4],
                                        unsigned b0, unsigned b1) {
    asm volatile(
        "mma.sync.aligned.m16n8k16.row.col.f32.f16.f16.f32 "
        "{%0,%1,%2,%3}, {%4,%5,%6,%7}, {%8,%9}, {%0,%1,%2,%3};"
        : "+f"(d[0]), "+f"(d[1]), "+f"(d[2]), "+f"(d[3])
        : "r"(a[0]), "r"(a[1]), "r"(a[2]), "r"(a[3]), "r"(b0), "r"(b1));
}
__device__ __forceinline__ unsigned smem_u32(const void* p) {
    unsigned a;
    asm("{ .reg .u64 t; cvta.to.shared.u64 t, %1; cvt.u32.u64 %0, t; }" : "=r"(a) : "l"(p));
    return a;
}
__device__ __forceinline__ void cp16(unsigned dst, const void* src) {
    asm volatile("cp.async.cg.shared.global [%0], [%1], 16;" :: "r"(dst), "l"(src) : "memory");
}
#define CP_COMMIT() asm volatile("cp.async.commit_group;" ::: "memory")
#define CP_WAIT1()  asm volatile("cp.async.wait_group 1;" ::: "memory")
#define CP_WAIT0()  asm volatile("cp.async.wait_group 0;" ::: "memory")

// ---------- K0: detect int64 vs int32 targets ----------
__global__ void detect_kernel(const int* __restrict__ t32) {
    __shared__ int sred[256];
    int tid = threadIdx.x;
    int v = 0;
    for (int i = tid; i < B_SZ / 2; i += 256) v |= t32[2 * i + 1];
    sred[tid] = v;
    __syncthreads();
    for (int s = 128; s; s >>= 1) {
        if (tid < s) sred[tid] |= sred[tid + s];
        __syncthreads();
    }
    if (tid == 0) g_is64 = (sred[0] == 0) ? 1 : 0;
}

// ---------- K1: sum-of-squares + CE + fp16 copy + minmax init ----------
__global__ void rowstats_kernel(const float* __restrict__ logits, const void* __restrict__ targets) {
    int lane = threadIdx.x & 31;
    int row = (blockIdx.x << 3) + (threadIdx.x >> 5);
    float4 v = reinterpret_cast<const float4*>(logits)[row * 32 + lane];
    {
        __half2 h0 = __floats2half2_rn(v.x, v.y);
        __half2 h1 = __floats2half2_rn(v.z, v.w);
        reinterpret_cast<uint2*>(g_xh)[row * 32 + lane] =
            make_uint2(*reinterpret_cast<unsigned*>(&h0), *reinterpret_cast<unsigned*>(&h1));
    }
    float ss = fmaf(v.x, v.x, fmaf(v.y, v.y, fmaf(v.z, v.z, v.w * v.w)));
    float mx = fmaxf(fmaxf(v.x, v.y), fmaxf(v.z, v.w));
#pragma unroll
    for (int o = 16; o; o >>= 1) {
        ss += __shfl_xor_sync(0xffffffffu, ss, o);
        mx = fmaxf(mx, __shfl_xor_sync(0xffffffffu, mx, o));
    }
    float se = expf(v.x - mx) + expf(v.y - mx) + expf(v.z - mx) + expf(v.w - mx);
#pragma unroll
    for (int o = 16; o; o >>= 1) se += __shfl_xor_sync(0xffffffffu, se, o);
    int t = g_is64 ? (int)((const long long*)targets)[row] : ((const int*)targets)[row];
    int c = t & 3;
    float tv = (c == 0) ? v.x : (c == 1) ? v.y : (c == 2) ? v.z : v.w;
    tv = __shfl_sync(0xffffffffu, tv, t >> 2);
    if (lane == 0) {
        g_sq[row] = ss;
        g_ce[row] = mx + logf(se) - tv;
        g_pm[row] = 0u;             // encode-min
        g_pn[row] = 0xFFFFFFFFu;    // encode-max
    }
}

// ---------- K2: symmetric fp16 MMA Gram + two-sided batch-hard mining ----------
// 130 CTAs x 16 upper-triangular tiles each. 8 warps: warp (wrow=wid&3, wcol=wid>>2),
// warp tile 32x64. A strip in smem (reloaded on tile-row change), B double-buffered.
extern __shared__ __half s_all[];   // A: [0,BUF_H) ; B0: [BUF_H,2BUF_H) ; B1: [2BUF_H,3BUF_H)

__global__ void __launch_bounds__(256, 1)
triplet_mma_kernel(const void* __restrict__ targets) {
    __shared__ __align__(16) uint2 s_sjt[2][TN];   // {sq_j bits, t_j}
    __shared__ int   s_ta[TM];
    __shared__ float s_sqa[TM];

    const int tid  = threadIdx.x;
    const int lane = tid & 31;
    const int wid  = tid >> 5;
    const int warp_m = (wid & 3) * 32;
    const int warp_n = (wid >> 2) * 64;
    const int g = lane >> 2, tq = lane & 3;
    const int is64 = g_is64;

    // ---- first tile (i,j) of this CTA ----
    int T0 = blockIdx.x * TPC;
    int ti = 0, rem = T0;
    while (rem >= S_STRIPS - ti) { rem -= S_STRIPS - ti; ti++; }
    int tj = ti + rem;

    __half* s_a = s_all;

    // load A strip (plain loads), s_ta, s_sqa
    {
        const uint4* Xu = reinterpret_cast<const uint4*>(g_xh);
        for (int e = tid; e < TM * 16; e += 256) {
            int n = e >> 4, q = e & 15;
            *reinterpret_cast<uint4*>(&s_a[n * BSTRIDE_H + q * 8]) = Xu[(ti * TM + n) * 16 + q];
        }
        if (tid < TM) {
            int r = ti * TM + tid;
            s_ta[tid] = is64 ? (int)((const long long*)targets)[r] : ((const int*)targets)[r];
            s_sqa[tid] = g_sq[r];
        }
    }
    // prefetch B tile 0
    {
        int j0 = tj * TN;
        unsigned sb = smem_u32(s_all) + (unsigned)BUF_H * 2u;
        for (int e = tid; e < TN * 16; e += 256) {
            int n = e >> 4, q = e & 15;
            cp16(sb + (unsigned)(n * BSTRIDE_H + q * 8) * 2u, &g_xh[(j0 + n) * D_SZ + q * 8]);
        }
        if (tid < TN) {
            int t = is64 ? (int)((const long long*)targets)[j0 + tid]
                         : ((const int*)targets)[j0 + tid];
            s_sjt[0][tid] = make_uint2(__float_as_uint(g_sq[j0 + tid]), (unsigned)t);
        }
        CP_COMMIT();
    }
    __syncthreads();

    int ta2[2][2];
    float sqa4[4];
    int reg_i = ti;
#pragma unroll
    for (int mf = 0; mf < 2; mf++)
#pragma unroll
        for (int h = 0; h < 2; h++) {
            int r = warp_m + mf * 16 + g + 8 * h;
            ta2[mf][h] = s_ta[r];
            sqa4[2 * mf + h] = s_sqa[r];
        }

    float runm[4], runn[4];
#pragma unroll
    for (int s = 0; s < 4; s++) { runm[s] = -INFINITY; runn[s] = INFINITY; }

    for (int t = 0; t < TPC; t++) {
        const int cur = t & 1, nxt = cur ^ 1;
        // next tile coords
        int ni = ti, nj = tj + 1;
        if (nj == S_STRIPS) { ni = ti + 1; nj = ni; }
        const bool last = (t == TPC - 1);
        const bool rowchg = (!last) && (ni != ti);

        // reload regs if strip changed at previous boundary (smem synced already)
        if (reg_i != ti) {
            reg_i = ti;
#pragma unroll
            for (int mf = 0; mf < 2; mf++)
#pragma unroll
                for (int h = 0; h < 2; h++) {
                    int r = warp_m + mf * 16 + g + 8 * h;
                    ta2[mf][h] = s_ta[r];
                    sqa4[2 * mf + h] = s_sqa[r];
                }
        }

        // prefetch next B
        if (!last) {
            int j0 = nj * TN;
            unsigned sb = smem_u32(s_all) + (unsigned)(BUF_H * (1 + nxt)) * 2u;
            for (int e = tid; e < TN * 16; e += 256) {
                int n = e >> 4, q = e & 15;
                cp16(sb + (unsigned)(n * BSTRIDE_H + q * 8) * 2u, &g_xh[(j0 + n) * D_SZ + q * 8]);
            }
            if (tid < TN) {
                int tt = is64 ? (int)((const long long*)targets)[j0 + tid]
                              : ((const int*)targets)[j0 + tid];
                s_sjt[nxt][tid] = make_uint2(__float_as_uint(g_sq[j0 + tid]), (unsigned)tt);
            }
            CP_COMMIT();
            CP_WAIT1();
        } else {
            CP_WAIT0();
        }
        __syncthreads();

        // ---- MMA 32x64 over K=128 ----
        float d[2][8][4];
#pragma unroll
        for (int mf = 0; mf < 2; mf++)
#pragma unroll
            for (int nf = 0; nf < 8; nf++)
#pragma unroll
                for (int r = 0; r < 4; r++) d[mf][nf][r] = 0.0f;

        const __half* pa = s_a + (warp_m + g) * BSTRIDE_H + tq * 2;
        const __half* bb = s_all + BUF_H * (1 + cur) + (warp_n + g) * BSTRIDE_H + tq * 2;
#pragma unroll
        for (int s = 0; s < 8; s++) {
            unsigned af[2][4];
#pragma unroll
            for (int mf = 0; mf < 2; mf++) {
                const __half* p = pa + mf * 16 * BSTRIDE_H + s * 16;
                af[mf][0] = *reinterpret_cast<const unsigned*>(p);
                af[mf][1] = *reinterpret_cast<const unsigned*>(p + 8 * BSTRIDE_H);
                af[mf][2] = *reinterpret_cast<const unsigned*>(p + 8);
                af[mf][3] = *reinterpret_cast<const unsigned*>(p + 8 * BSTRIDE_H + 8);
            }
            unsigned bf[8][2];
#pragma unroll
            for (int nf = 0; nf < 8; nf++) {
                bf[nf][0] = *reinterpret_cast<const unsigned*>(bb + nf * 8 * BSTRIDE_H + s * 16);
                bf[nf][1] = *reinterpret_cast<const unsigned*>(bb + nf * 8 * BSTRIDE_H + s * 16 + 8);
            }
#pragma unroll
            for (int mf = 0; mf < 2; mf++)
#pragma unroll
                for (int nf = 0; nf < 8; nf++)
                    mma_f16(d[mf][nf], af[mf], bf[nf][0], bf[nf][1]);
        }

        // ---- two-sided epilogue ----
        float colm[8][2], coln[8][2];
#pragma unroll
        for (int nf = 0; nf < 8; nf++)
#pragma unroll
            for (int p = 0; p < 2; p++) { colm[nf][p] = -INFINITY; coln[nf][p] = INFINITY; }

#pragma unroll
        for (int nf = 0; nf < 8; nf++) {
            int colp = warp_n + nf * 8 + 2 * tq;
            uint4 pjt = *reinterpret_cast<const uint4*>(&s_sjt[cur][colp]);
            float sq0 = __uint_as_float(pjt.x); int t0 = (int)pjt.y;
            float sq1 = __uint_as_float(pjt.z); int t1 = (int)pjt.w;
#pragma unroll
            for (int mf = 0; mf < 2; mf++) {
                int s0 = 2 * mf, s1 = 2 * mf + 1;
                {
                    float vr = fmaf(-2.0f, d[mf][nf][0], sq0);
                    float vc = fmaf(-2.0f, d[mf][nf][0], sqa4[s0]);
                    if (t0 == ta2[mf][0]) { runm[s0] = fmaxf(runm[s0], vr); colm[nf][0] = fmaxf(colm[nf][0], vc); }
                    else                  { runn[s0] = fminf(runn[s0], vr); coln[nf][0] = fminf(coln[nf][0], vc); }
                }
                {
                    float vr = fmaf(-2.0f, d[mf][nf][1], sq1);
                    float vc = fmaf(-2.0f, d[mf][nf][1], sqa4[s0]);
                    if (t1 == ta2[mf][0]) { runm[s0] = fmaxf(runm[s0], vr); colm[nf][1] = fmaxf(colm[nf][1], vc); }
                    else                  { runn[s0] = fminf(runn[s0], vr); coln[nf][1] = fminf(coln[nf][1], vc); }
                }
                {
                    float vr = fmaf(-2.0f, d[mf][nf][2], sq0);
                    float vc = fmaf(-2.0f, d[mf][nf][2], sqa4[s1]);
                    if (t0 == ta2[mf][1]) { runm[s1] = fmaxf(runm[s1], vr); colm[nf][0] = fmaxf(colm[nf][0], vc); }
                    else                  { runn[s1] = fminf(runn[s1], vr); coln[nf][0] = fminf(coln[nf][0], vc); }
                }
                {
                    float vr = fmaf(-2.0f, d[mf][nf][3], sq1);
                    float vc = fmaf(-2.0f, d[mf][nf][3], sqa4[s1]);
                    if (t1 == ta2[mf][1]) { runm[s1] = fmaxf(runm[s1], vr); colm[nf][1] = fmaxf(colm[nf][1], vc); }
                    else                  { runn[s1] = fminf(runn[s1], vr); coln[nf][1] = fminf(coln[nf][1], vc); }
                }
            }
        }

        // ---- col flush (every tile): reduce over g-lanes, atomics ----
        {
            const int j0 = tj * TN;
#pragma unroll
            for (int nf = 0; nf < 8; nf++)
#pragma unroll
                for (int p = 0; p < 2; p++) {
                    float m = colm[nf][p], n = coln[nf][p];
                    m = fmaxf(m, __shfl_xor_sync(0xffffffffu, m, 4));
                    m = fmaxf(m, __shfl_xor_sync(0xffffffffu, m, 8));
                    m = fmaxf(m, __shfl_xor_sync(0xffffffffu, m, 16));
                    n = fminf(n, __shfl_xor_sync(0xffffffffu, n, 4));
                    n = fminf(n, __shfl_xor_sync(0xffffffffu, n, 8));
                    n = fminf(n, __shfl_xor_sync(0xffffffffu, n, 16));
                    if (lane < 4) {
                        int gc = j0 + warp_n + nf * 8 + 2 * lane + p;
                        atomicMax(&g_pm[gc], encf(m));
                        atomicMin(&g_pn[gc], encf(n));
                    }
                }
        }

        // ---- row flush on strip change / end ----
        if (last || rowchg) {
            const int i0 = ti * TM;
#pragma unroll
            for (int slot = 0; slot < 4; slot++) {
                float m = runm[slot], n = runn[slot];
                m = fmaxf(m, __shfl_xor_sync(0xffffffffu, m, 1));
                m = fmaxf(m, __shfl_xor_sync(0xffffffffu, m, 2));
                n = fminf(n, __shfl_xor_sync(0xffffffffu, n, 1));
                n = fminf(n, __shfl_xor_sync(0xffffffffu, n, 2));
                if (tq == 0) {
                    int r = i0 + warp_m + (slot >> 1) * 16 + g + 8 * (slot & 1);
                    atomicMax(&g_pm[r], encf(m));
                    atomicMin(&g_pn[r], encf(n));
                }
                runm[slot] = -INFINITY; runn[slot] = INFINITY;
            }
        }
        // ---- reload A strip if next tile is a new row ----
        if (rowchg) {
            __syncthreads();   // everyone done reading s_a / s_ta for this strip
            const uint4* Xu = reinterpret_cast<const uint4*>(g_xh);
            for (int e = tid; e < TM * 16; e += 256) {
                int n = e >> 4, q = e & 15;
                *reinterpret_cast<uint4*>(&s_a[n * BSTRIDE_H + q * 8]) = Xu[(ni * TM + n) * 16 + q];
            }
            if (tid < TM) {
                int r = ni * TM + tid;
                s_ta[tid] = is64 ? (int)((const long long*)targets)[r] : ((const int*)targets)[r];
                s_sqa[tid] = g_sq[r];
            }
        }
        __syncthreads();   // protects B cur buffer reuse + new A/s_ta visibility
        ti = ni; tj = nj;
    }
}

// ---------- K3: reduction (fp64 adds) + fp32 Lambert-W tail ----------
__global__ void __launch_bounds__(1024, 1) fin_kernel(float* __restrict__ out) {
    __shared__ double s_rt[32], s_rc[32];
    int tid = threadIdx.x;
    int lane = tid & 31, wid = tid >> 5;
    double st = 0.0, sc = 0.0;
#pragma unroll
    for (int a = tid; a < B_SZ; a += 1024) {
        float m = decf(g_pm[a]);
        float n = decf(g_pn[a]);
        float sqi = g_sq[a];
        float dap = sqrtf(fmaxf(sqi + m, 1e-12f));
        float dan = sqrtf(fmaxf(sqi + n, 1e-12f));
        st += (double)fmaxf(dap - dan + 0.3f, 0.0f);
        sc += (double)g_ce[a];
    }
#pragma unroll
    for (int o = 16; o; o >>= 1) {
        st += __shfl_down_sync(0xffffffffu, st, o);
        sc += __shfl_down_sync(0xffffffffu, sc, o);
    }
    if (lane == 0) { s_rt[wid] = st; s_rc[wid] = sc; }
    __syncthreads();
    if (wid == 0) {
        double t0 = (lane < 32) ? s_rt[lane] : 0.0;
        double c0 = (lane < 32) ? s_rc[lane] : 0.0;
#pragma unroll
        for (int o = 16; o; o >>= 1) {
            t0 += __shfl_down_sync(0xffffffffu, t0, o);
            c0 += __shfl_down_sync(0xffffffffu, c0, o);
        }
        if (lane == 0) {
            // fp32 tail — matches the fp32 reference computation
            const float LAM = 0.25f;
            const float TAU = logf(128.0f);
            float ce = (float)(c0 / (double)B_SZ);
            float l  = (float)(t0 / (double)B_SZ);
            float e1 = expf(1.0f);
            float z = 0.5f * fmaxf(-2.0f / e1, (l - TAU) / LAM);
            float pv = sqrtf(fmaxf(2.0f * (e1 * z + 1.0f), 0.0f));
            float wn = -1.0f + pv - pv * pv * (1.0f / 3.0f) + (11.0f / 72.0f) * pv * pv * pv;
            float w = (z < 0.0f) ? wn : log1pf(fmaxf(z, 0.0f));
#pragma unroll
            for (int it = 0; it < 8; it++) {
                float ew = expf(w);
                float f = fmaf(w, ew, -z);
                float wp1 = w + 1.0f;
                w = w - f / (ew * wp1 - (w + 2.0f) * f / (2.0f * wp1));
            }
            float sigma = expf(-w);
            float ls = logf(sigma);
            float loss = (ce - TAU) * sigma + LAM * ls * ls;
            out[0] = loss / (float)B_SZ;
        }
    }
}

extern "C" void kernel_launch(void* const* d_in, const int* in_sizes, int n_in,
                              void* d_out, int out_size) {
    const float* logits = (const float*)d_in[0];
    const void* targets = d_in[1];
    float* out = (float*)d_out;
    (void)in_sizes; (void)n_in; (void)out_size;

    const int smem_bytes = 3 * BUF_H * (int)sizeof(__half);   // 104448
    cudaFuncSetAttribute(triplet_mma_kernel, cudaFuncAttributeMaxDynamicSharedMemorySize,
                         smem_bytes);

    detect_kernel<<<1, 256>>>((const int*)targets);
    rowstats_kernel<<<B_SZ / 8, 256>>>(logits, targets);
    triplet_mma_kernel<<<NCTA, 256, smem_bytes>>>(targets);
    fin_kernel<<<1, 1024>>>(out);
}

// round 7
// speedup vs baseline: 9.5983x; 1.1216x over previous
#include <cuda_runtime.h>
#include <cuda_fp16.h>
#include <math.h>
#include <stdint.h>

#define B_SZ 8192
#define D_SZ 128
#define TM 128
#define TN 128
#define S_STRIPS (B_SZ / TM)             // 64
#define TILES_TOT (S_STRIPS * (S_STRIPS + 1) / 2)   // 2080
#define NCTA 130
#define TPC (TILES_TOT / NCTA)           // 16
#define BSTRIDE_H 136                    // padded smem row stride (halfs), conflict-free
#define BUF_H (TN * BSTRIDE_H)

__device__ __half   g_xh[B_SZ * D_SZ];
__device__ float    g_sq[B_SZ];
__device__ float    g_ce[B_SZ];
__device__ unsigned g_pm[B_SZ];          // order-encoded float max (pos candidates)
__device__ unsigned g_pn[B_SZ];          // order-encoded float min (neg candidates)
__device__ double   g_part_tr[32];
__device__ double   g_part_ce[32];
__device__ int      g_is64;

// ---------------- helpers ----------------
__device__ __forceinline__ unsigned encf(float f) {
    unsigned u = __float_as_uint(f);
    return ((int)u < 0) ? ~u : (u | 0x80000000u);
}
__device__ __forceinline__ float decf(unsigned u) {
    return (u & 0x80000000u) ? __uint_as_float(u & 0x7fffffffu) : __uint_as_float(~u);
}
__device__ __forceinline__ void mma_f16(float d[4], const unsigned a[4],
                                        unsigned b0, unsigned b1) {
    asm volatile(
        "mma.sync.aligned.m16n8k16.row.col.f32.f16.f16.f32 "
        "{%0,%1,%2,%3}, {%4,%5,%6,%7}, {%8,%9}, {%0,%1,%2,%3};"
        : "+f"(d[0]), "+f"(d[1]), "+f"(d[2]), "+f"(d[3])
        : "r"(a[0]), "r"(a[1]), "r"(a[2]), "r"(a[3]), "r"(b0), "r"(b1));
}
__device__ __forceinline__ void ldsm_x4(unsigned& r0, unsigned& r1, unsigned& r2, unsigned& r3,
                                        unsigned addr) {
    asm volatile("ldmatrix.sync.aligned.m8n8.x4.shared.b16 {%0,%1,%2,%3}, [%4];"
                 : "=r"(r0), "=r"(r1), "=r"(r2), "=r"(r3) : "r"(addr));
}
__device__ __forceinline__ unsigned smem_u32(const void* p) {
    unsigned a;
    asm("{ .reg .u64 t; cvta.to.shared.u64 t, %1; cvt.u32.u64 %0, t; }" : "=r"(a) : "l"(p));
    return a;
}
__device__ __forceinline__ void cp16(unsigned dst, const void* src) {
    asm volatile("cp.async.cg.shared.global [%0], [%1], 16;" :: "r"(dst), "l"(src) : "memory");
}
#define CP_COMMIT() asm volatile("cp.async.commit_group;" ::: "memory")
#define CP_WAIT1()  asm volatile("cp.async.wait_group 1;" ::: "memory")
#define CP_WAIT0()  asm volatile("cp.async.wait_group 0;" ::: "memory")

// ---------- K0: detect int64 vs int32 targets ----------
__global__ void detect_kernel(const int* __restrict__ t32) {
    __shared__ int sred[512];
    int tid = threadIdx.x;
    int v = 0;
    for (int i = tid; i < B_SZ / 2; i += 512) v |= t32[2 * i + 1];
    sred[tid] = v;
    __syncthreads();
    for (int s = 256; s; s >>= 1) {
        if (tid < s) sred[tid] |= sred[tid + s];
        __syncthreads();
    }
    if (tid == 0) g_is64 = (sred[0] == 0) ? 1 : 0;
}

// ---------- K1: sum-of-squares + CE + fp16 copy + minmax init ----------
__global__ void rowstats_kernel(const float* __restrict__ logits, const void* __restrict__ targets) {
    int lane = threadIdx.x & 31;
    int row = (blockIdx.x << 3) + (threadIdx.x >> 5);
    float4 v = reinterpret_cast<const float4*>(logits)[row * 32 + lane];
    {
        __half2 h0 = __floats2half2_rn(v.x, v.y);
        __half2 h1 = __floats2half2_rn(v.z, v.w);
        reinterpret_cast<uint2*>(g_xh)[row * 32 + lane] =
            make_uint2(*reinterpret_cast<unsigned*>(&h0), *reinterpret_cast<unsigned*>(&h1));
    }
    float ss = fmaf(v.x, v.x, fmaf(v.y, v.y, fmaf(v.z, v.z, v.w * v.w)));
    float mx = fmaxf(fmaxf(v.x, v.y), fmaxf(v.z, v.w));
#pragma unroll
    for (int o = 16; o; o >>= 1) {
        ss += __shfl_xor_sync(0xffffffffu, ss, o);
        mx = fmaxf(mx, __shfl_xor_sync(0xffffffffu, mx, o));
    }
    float se = expf(v.x - mx) + expf(v.y - mx) + expf(v.z - mx) + expf(v.w - mx);
#pragma unroll
    for (int o = 16; o; o >>= 1) se += __shfl_xor_sync(0xffffffffu, se, o);
    int t = g_is64 ? (int)((const long long*)targets)[row] : ((const int*)targets)[row];
    int c = t & 3;
    float tv = (c == 0) ? v.x : (c == 1) ? v.y : (c == 2) ? v.z : v.w;
    tv = __shfl_sync(0xffffffffu, tv, t >> 2);
    if (lane == 0) {
        g_sq[row] = ss;
        g_ce[row] = mx + logf(se) - tv;
        g_pm[row] = 0u;             // encode-min
        g_pn[row] = 0xFFFFFFFFu;    // encode-max
    }
}

// ---------- K2: symmetric fp16 MMA Gram + two-sided batch-hard mining ----------
extern __shared__ __half s_all[];   // A: [0,BUF_H) ; B0: [BUF_H,2BUF_H) ; B1: [2BUF_H,3BUF_H)

__global__ void __launch_bounds__(256, 1)
triplet_mma_kernel(const void* __restrict__ targets) {
    __shared__ __align__(16) uint2 s_sjt[2][TN];   // {sq_j bits, t_j}
    __shared__ int   s_ta[TM];
    __shared__ float s_sqa[TM];

    const int tid  = threadIdx.x;
    const int lane = tid & 31;
    const int wid  = tid >> 5;
    const int warp_m = (wid & 3) * 32;
    const int warp_n = (wid >> 2) * 64;
    const int g = lane >> 2, tq = lane & 3;
    const int is64 = g_is64;
    const unsigned sbase = smem_u32(s_all);

    // ldmatrix lane-address bases (halfs)
    const unsigned a_lm = sbase + (unsigned)((warp_m + (lane & 15)) * BSTRIDE_H + (lane >> 4) * 8) * 2u;
    const unsigned b_lm_off = (unsigned)((warp_n + (lane & 7) + 8 * (lane >> 4)) * BSTRIDE_H
                                         + ((lane >> 3) & 1) * 8) * 2u;

    // ---- first tile (i,j) of this CTA ----
    int T0 = blockIdx.x * TPC;
    int ti = 0, rem = T0;
    while (rem >= S_STRIPS - ti) { rem -= S_STRIPS - ti; ti++; }
    int tj = ti + rem;

    __half* s_a = s_all;

    {
        const uint4* Xu = reinterpret_cast<const uint4*>(g_xh);
        for (int e = tid; e < TM * 16; e += 256) {
            int n = e >> 4, q = e & 15;
            *reinterpret_cast<uint4*>(&s_a[n * BSTRIDE_H + q * 8]) = Xu[(ti * TM + n) * 16 + q];
        }
        if (tid < TM) {
            int r = ti * TM + tid;
            s_ta[tid] = is64 ? (int)((const long long*)targets)[r] : ((const int*)targets)[r];
            s_sqa[tid] = g_sq[r];
        }
    }
    {
        int j0 = tj * TN;
        unsigned sb = sbase + (unsigned)BUF_H * 2u;
        for (int e = tid; e < TN * 16; e += 256) {
            int n = e >> 4, q = e & 15;
            cp16(sb + (unsigned)(n * BSTRIDE_H + q * 8) * 2u, &g_xh[(j0 + n) * D_SZ + q * 8]);
        }
        if (tid < TN) {
            int t = is64 ? (int)((const long long*)targets)[j0 + tid]
                         : ((const int*)targets)[j0 + tid];
            s_sjt[0][tid] = make_uint2(__float_as_uint(g_sq[j0 + tid]), (unsigned)t);
        }
        CP_COMMIT();
    }
    __syncthreads();

    int ta2[2][2];
    float sqa4[4];
    int reg_i = ti;
#pragma unroll
    for (int mf = 0; mf < 2; mf++)
#pragma unroll
        for (int h = 0; h < 2; h++) {
            int r = warp_m + mf * 16 + g + 8 * h;
            ta2[mf][h] = s_ta[r];
            sqa4[2 * mf + h] = s_sqa[r];
        }

    float runm[4], runn[4];
#pragma unroll
    for (int s = 0; s < 4; s++) { runm[s] = -INFINITY; runn[s] = INFINITY; }

    for (int t = 0; t < TPC; t++) {
        const int cur = t & 1, nxt = cur ^ 1;
        int ni = ti, nj = tj + 1;
        if (nj == S_STRIPS) { ni = ti + 1; nj = ni; }
        const bool last = (t == TPC - 1);
        const bool rowchg = (!last) && (ni != ti);

        if (reg_i != ti) {
            reg_i = ti;
#pragma unroll
            for (int mf = 0; mf < 2; mf++)
#pragma unroll
                for (int h = 0; h < 2; h++) {
                    int r = warp_m + mf * 16 + g + 8 * h;
                    ta2[mf][h] = s_ta[r];
                    sqa4[2 * mf + h] = s_sqa[r];
                }
        }

        if (!last) {
            int j0 = nj * TN;
            unsigned sb = sbase + (unsigned)(BUF_H * (1 + nxt)) * 2u;
            for (int e = tid; e < TN * 16; e += 256) {
                int n = e >> 4, q = e & 15;
                cp16(sb + (unsigned)(n * BSTRIDE_H + q * 8) * 2u, &g_xh[(j0 + n) * D_SZ + q * 8]);
            }
            if (tid < TN) {
                int tt = is64 ? (int)((const long long*)targets)[j0 + tid]
                              : ((const int*)targets)[j0 + tid];
                s_sjt[nxt][tid] = make_uint2(__float_as_uint(g_sq[j0 + tid]), (unsigned)tt);
            }
            CP_COMMIT();
            CP_WAIT1();
        } else {
            CP_WAIT0();
        }
        __syncthreads();

        // ---- MMA 32x64 over K=128, fragments via ldmatrix ----
        float d[2][8][4];
#pragma unroll
        for (int mf = 0; mf < 2; mf++)
#pragma unroll
            for (int nf = 0; nf < 8; nf++)
#pragma unroll
                for (int r = 0; r < 4; r++) d[mf][nf][r] = 0.0f;

        const unsigned b_lm = sbase + (unsigned)(BUF_H * (1 + cur)) * 2u + b_lm_off;
#pragma unroll
        for (int s = 0; s < 8; s++) {
            unsigned af[2][4];
            ldsm_x4(af[0][0], af[0][1], af[0][2], af[0][3], a_lm + s * 32);
            ldsm_x4(af[1][0], af[1][1], af[1][2], af[1][3],
                    a_lm + 16 * BSTRIDE_H * 2 + s * 32);
            unsigned bf[8][2];
#pragma unroll
            for (int u = 0; u < 4; u++)
                ldsm_x4(bf[2 * u][0], bf[2 * u][1], bf[2 * u + 1][0], bf[2 * u + 1][1],
                        b_lm + u * (16 * BSTRIDE_H * 2) + s * 32);
#pragma unroll
            for (int mf = 0; mf < 2; mf++)
#pragma unroll
                for (int nf = 0; nf < 8; nf++)
                    mma_f16(d[mf][nf], af[mf], bf[nf][0], bf[nf][1]);
        }

        // ---- two-sided epilogue ----
        float colm[8][2], coln[8][2];
#pragma unroll
        for (int nf = 0; nf < 8; nf++)
#pragma unroll
            for (int p = 0; p < 2; p++) { colm[nf][p] = -INFINITY; coln[nf][p] = INFINITY; }

#pragma unroll
        for (int nf = 0; nf < 8; nf++) {
            int colp = warp_n + nf * 8 + 2 * tq;
            uint4 pjt = *reinterpret_cast<const uint4*>(&s_sjt[cur][colp]);
            float sq0 = __uint_as_float(pjt.x); int t0 = (int)pjt.y;
            float sq1 = __uint_as_float(pjt.z); int t1 = (int)pjt.w;
#pragma unroll
            for (int mf = 0; mf < 2; mf++) {
                int s0 = 2 * mf, s1 = 2 * mf + 1;
                {
                    float vr = fmaf(-2.0f, d[mf][nf][0], sq0);
                    float vc = fmaf(-2.0f, d[mf][nf][0], sqa4[s0]);
                    if (t0 == ta2[mf][0]) { runm[s0] = fmaxf(runm[s0], vr); colm[nf][0] = fmaxf(colm[nf][0], vc); }
                    else                  { runn[s0] = fminf(runn[s0], vr); coln[nf][0] = fminf(coln[nf][0], vc); }
                }
                {
                    float vr = fmaf(-2.0f, d[mf][nf][1], sq1);
                    float vc = fmaf(-2.0f, d[mf][nf][1], sqa4[s0]);
                    if (t1 == ta2[mf][0]) { runm[s0] = fmaxf(runm[s0], vr); colm[nf][1] = fmaxf(colm[nf][1], vc); }
                    else                  { runn[s0] = fminf(runn[s0], vr); coln[nf][1] = fminf(coln[nf][1], vc); }
                }
                {
                    float vr = fmaf(-2.0f, d[mf][nf][2], sq0);
                    float vc = fmaf(-2.0f, d[mf][nf][2], sqa4[s1]);
                    if (t0 == ta2[mf][1]) { runm[s1] = fmaxf(runm[s1], vr); colm[nf][0] = fmaxf(colm[nf][0], vc); }
                    else                  { runn[s1] = fminf(runn[s1], vr); coln[nf][0] = fminf(coln[nf][0], vc); }
                }
                {
                    float vr = fmaf(-2.0f, d[mf][nf][3], sq1);
                    float vc = fmaf(-2.0f, d[mf][nf][3], sqa4[s1]);
                    if (t1 == ta2[mf][1]) { runm[s1] = fmaxf(runm[s1], vr); colm[nf][1] = fmaxf(colm[nf][1], vc); }
                    else                  { runn[s1] = fminf(runn[s1], vr); coln[nf][1] = fminf(coln[nf][1], vc); }
                }
            }
        }

        // ---- col flush (every tile) ----
        {
            const int j0 = tj * TN;
#pragma unroll
            for (int nf = 0; nf < 8; nf++)
#pragma unroll
                for (int p = 0; p < 2; p++) {
                    float m = colm[nf][p], n = coln[nf][p];
                    m = fmaxf(m, __shfl_xor_sync(0xffffffffu, m, 4));
                    m = fmaxf(m, __shfl_xor_sync(0xffffffffu, m, 8));
                    m = fmaxf(m, __shfl_xor_sync(0xffffffffu, m, 16));
                    n = fminf(n, __shfl_xor_sync(0xffffffffu, n, 4));
                    n = fminf(n, __shfl_xor_sync(0xffffffffu, n, 8));
                    n = fminf(n, __shfl_xor_sync(0xffffffffu, n, 16));
                    if (lane < 4) {
                        int gc = j0 + warp_n + nf * 8 + 2 * lane + p;
                        atomicMax(&g_pm[gc], encf(m));
                        atomicMin(&g_pn[gc], encf(n));
                    }
                }
        }

        // ---- row flush on strip change / end ----
        if (last || rowchg) {
            const int i0 = ti * TM;
#pragma unroll
            for (int slot = 0; slot < 4; slot++) {
                float m = runm[slot], n = runn[slot];
                m = fmaxf(m, __shfl_xor_sync(0xffffffffu, m, 1));
                m = fmaxf(m, __shfl_xor_sync(0xffffffffu, m, 2));
                n = fminf(n, __shfl_xor_sync(0xffffffffu, n, 1));
                n = fminf(n, __shfl_xor_sync(0xffffffffu, n, 2));
                if (tq == 0) {
                    int r = i0 + warp_m + (slot >> 1) * 16 + g + 8 * (slot & 1);
                    atomicMax(&g_pm[r], encf(m));
                    atomicMin(&g_pn[r], encf(n));
                }
                runm[slot] = -INFINITY; runn[slot] = INFINITY;
            }
        }
        if (rowchg) {
            __syncthreads();
            const uint4* Xu = reinterpret_cast<const uint4*>(g_xh);
            for (int e = tid; e < TM * 16; e += 256) {
                int n = e >> 4, q = e & 15;
                *reinterpret_cast<uint4*>(&s_a[n * BSTRIDE_H + q * 8]) = Xu[(ni * TM + n) * 16 + q];
            }
            if (tid < TM) {
                int r = ni * TM + tid;
                s_ta[tid] = is64 ? (int)((const long long*)targets)[r] : ((const int*)targets)[r];
                s_sqa[tid] = g_sq[r];
            }
        }
        __syncthreads();
        ti = ni; tj = nj;
    }
}

// ---------- K3a: parallel partial sums (32 blocks) ----------
__global__ void fin1_kernel() {
    __shared__ double s_rt[8], s_rc[8];
    int tid = threadIdx.x;
    int lane = tid & 31, wid = tid >> 5;
    int a = blockIdx.x * 256 + tid;
    float m = decf(g_pm[a]);
    float n = decf(g_pn[a]);
    float sqi = g_sq[a];
    float dap = sqrtf(fmaxf(sqi + m, 1e-12f));
    float dan = sqrtf(fmaxf(sqi + n, 1e-12f));
    double st = (double)fmaxf(dap - dan + 0.3f, 0.0f);
    double sc = (double)g_ce[a];
#pragma unroll
    for (int o = 16; o; o >>= 1) {
        st += __shfl_down_sync(0xffffffffu, st, o);
        sc += __shfl_down_sync(0xffffffffu, sc, o);
    }
    if (lane == 0) { s_rt[wid] = st; s_rc[wid] = sc; }
    __syncthreads();
    if (tid == 0) {
        double t0 = 0.0, c0 = 0.0;
#pragma unroll
        for (int w = 0; w < 8; w++) { t0 += s_rt[w]; c0 += s_rc[w]; }
        g_part_tr[blockIdx.x] = t0;
        g_part_ce[blockIdx.x] = c0;
    }
}

// ---------- K3b: final 32 partials + fp32 Lambert-W tail ----------
__global__ void fin2_kernel(float* __restrict__ out) {
    int lane = threadIdx.x;
    double t0 = g_part_tr[lane];
    double c0 = g_part_ce[lane];
#pragma unroll
    for (int o = 16; o; o >>= 1) {
        t0 += __shfl_down_sync(0xffffffffu, t0, o);
        c0 += __shfl_down_sync(0xffffffffu, c0, o);
    }
    if (lane == 0) {
        const float LAM = 0.25f;
        const float TAU = logf(128.0f);
        float ce = (float)(c0 / (double)B_SZ);
        float l  = (float)(t0 / (double)B_SZ);
        float e1 = expf(1.0f);
        float z = 0.5f * fmaxf(-2.0f / e1, (l - TAU) / LAM);
        float pv = sqrtf(fmaxf(2.0f * (e1 * z + 1.0f), 0.0f));
        float wn = -1.0f + pv - pv * pv * (1.0f / 3.0f) + (11.0f / 72.0f) * pv * pv * pv;
        float w = (z < 0.0f) ? wn : log1pf(fmaxf(z, 0.0f));
#pragma unroll
        for (int it = 0; it < 8; it++) {
            float ew = expf(w);
            float f = fmaf(w, ew, -z);
            float wp1 = w + 1.0f;
            w = w - f / (ew * wp1 - (w + 2.0f) * f / (2.0f * wp1));
        }
        float sigma = expf(-w);
        float ls = logf(sigma);
        float loss = (ce - TAU) * sigma + LAM * ls * ls;
        out[0] = loss / (float)B_SZ;
    }
}

extern "C" void kernel_launch(void* const* d_in, const int* in_sizes, int n_in,
                              void* d_out, int out_size) {
    const float* logits = (const float*)d_in[0];
    const void* targets = d_in[1];
    float* out = (float*)d_out;
    (void)in_sizes; (void)n_in; (void)out_size;

    const int smem_bytes = 3 * BUF_H * (int)sizeof(__half);   // 104448
    cudaFuncSetAttribute(triplet_mma_kernel, cudaFuncAttributeMaxDynamicSharedMemorySize,
                         smem_bytes);

    detect_kernel<<<1, 512>>>((const int*)targets);
    rowstats_kernel<<<B_SZ / 8, 256>>>(logits, targets);
    triplet_mma_kernel<<<NCTA, 256, smem_bytes>>>(targets);
    fin1_kernel<<<32, 256>>>();
    fin2_kernel<<<1, 32>>>(out);
}

// round 8
// speedup vs baseline: 9.6504x; 1.0054x over previous
#include <cuda_runtime.h>
#include <cuda_fp16.h>
#include <math.h>
#include <stdint.h>

#define B_SZ 8192
#define D_SZ 128
#define TM 128
#define TN 128
#define S_STRIPS (B_SZ / TM)             // 64
#define TILES_TOT (S_STRIPS * (S_STRIPS + 1) / 2)   // 2080
#define NCTA 260
#define TPC (TILES_TOT / NCTA)           // 8
#define BSTRIDE_H 136                    // padded smem row stride (halfs), conflict-free
#define BUF_H (TN * BSTRIDE_H)

__device__ __half   g_xh[B_SZ * D_SZ];
__device__ float    g_sq[B_SZ];
__device__ float    g_ce[B_SZ];
__device__ unsigned g_pm[B_SZ];          // order-encoded float max (pos candidates)
__device__ unsigned g_pn[B_SZ];          // order-encoded float min (neg candidates)
__device__ unsigned g_done;
__device__ int      g_is64;

// ---------------- helpers ----------------
__device__ __forceinline__ unsigned encf(float f) {
    unsigned u = __float_as_uint(f);
    return ((int)u < 0) ? ~u : (u | 0x80000000u);
}
__device__ __forceinline__ float decf(unsigned u) {
    return (u & 0x80000000u) ? __uint_as_float(u & 0x7fffffffu) : __uint_as_float(~u);
}
__device__ __forceinline__ void mma_f16(float d[4], const unsigned a[4],
                                        unsigned b0, unsigned b1) {
    asm volatile(
        "mma.sync.aligned.m16n8k16.row.col.f32.f16.f16.f32 "
        "{%0,%1,%2,%3}, {%4,%5,%6,%7}, {%8,%9}, {%0,%1,%2,%3};"
        : "+f"(d[0]), "+f"(d[1]), "+f"(d[2]), "+f"(d[3])
        : "r"(a[0]), "r"(a[1]), "r"(a[2]), "r"(a[3]), "r"(b0), "r"(b1));
}
__device__ __forceinline__ void ldsm_x4(unsigned& r0, unsigned& r1, unsigned& r2, unsigned& r3,
                                        unsigned addr) {
    asm volatile("ldmatrix.sync.aligned.m8n8.x4.shared.b16 {%0,%1,%2,%3}, [%4];"
                 : "=r"(r0), "=r"(r1), "=r"(r2), "=r"(r3) : "r"(addr));
}
__device__ __forceinline__ unsigned smem_u32(const void* p) {
    unsigned a;
    asm("{ .reg .u64 t; cvta.to.shared.u64 t, %1; cvt.u32.u64 %0, t; }" : "=r"(a) : "l"(p));
    return a;
}
__device__ __forceinline__ void cp16(unsigned dst, const void* src) {
    asm volatile("cp.async.cg.shared.global [%0], [%1], 16;" :: "r"(dst), "l"(src) : "memory");
}
#define CP_COMMIT() asm volatile("cp.async.commit_group;" ::: "memory")
#define CP_WAIT1()  asm volatile("cp.async.wait_group 1;" ::: "memory")
#define CP_WAIT0()  asm volatile("cp.async.wait_group 0;" ::: "memory")

// ---------- K0: detect int64 vs int32 targets (+ reset ticket) ----------
__global__ void detect_kernel(const int* __restrict__ t32) {
    __shared__ int sred[512];
    int tid = threadIdx.x;
    int v = 0;
    for (int i = tid; i < B_SZ / 2; i += 512) v |= t32[2 * i + 1];
    sred[tid] = v;
    __syncthreads();
    for (int s = 256; s; s >>= 1) {
        if (tid < s) sred[tid] |= sred[tid + s];
        __syncthreads();
    }
    if (tid == 0) {
        g_is64 = (sred[0] == 0) ? 1 : 0;
        g_done = 0u;
    }
}

// ---------- K1: sum-of-squares + CE + fp16 copy + minmax init ----------
__global__ void rowstats_kernel(const float* __restrict__ logits, const void* __restrict__ targets) {
    int lane = threadIdx.x & 31;
    int row = (blockIdx.x << 3) + (threadIdx.x >> 5);
    float4 v = reinterpret_cast<const float4*>(logits)[row * 32 + lane];
    {
        __half2 h0 = __floats2half2_rn(v.x, v.y);
        __half2 h1 = __floats2half2_rn(v.z, v.w);
        reinterpret_cast<uint2*>(g_xh)[row * 32 + lane] =
            make_uint2(*reinterpret_cast<unsigned*>(&h0), *reinterpret_cast<unsigned*>(&h1));
    }
    float ss = fmaf(v.x, v.x, fmaf(v.y, v.y, fmaf(v.z, v.z, v.w * v.w)));
    float mx = fmaxf(fmaxf(v.x, v.y), fmaxf(v.z, v.w));
#pragma unroll
    for (int o = 16; o; o >>= 1) {
        ss += __shfl_xor_sync(0xffffffffu, ss, o);
        mx = fmaxf(mx, __shfl_xor_sync(0xffffffffu, mx, o));
    }
    float se = expf(v.x - mx) + expf(v.y - mx) + expf(v.z - mx) + expf(v.w - mx);
#pragma unroll
    for (int o = 16; o; o >>= 1) se += __shfl_xor_sync(0xffffffffu, se, o);
    int t = g_is64 ? (int)((const long long*)targets)[row] : ((const int*)targets)[row];
    int c = t & 3;
    float tv = (c == 0) ? v.x : (c == 1) ? v.y : (c == 2) ? v.z : v.w;
    tv = __shfl_sync(0xffffffffu, tv, t >> 2);
    if (lane == 0) {
        g_sq[row] = ss;
        g_ce[row] = mx + logf(se) - tv;
        g_pm[row] = 0u;             // encode-min
        g_pn[row] = 0xFFFFFFFFu;    // encode-max
    }
}

// ---------- K2: symmetric fp16 MMA Gram + mining + fused finalize ----------
extern __shared__ __half s_all[];   // A: [0,BUF_H) ; B0: [BUF_H,2BUF_H) ; B1: [2BUF_H,3BUF_H)

__global__ void __launch_bounds__(256, 2)
triplet_mma_kernel(const void* __restrict__ targets, float* __restrict__ out) {
    __shared__ __align__(16) uint2 s_sjt[2][TN];   // {sq_j bits, t_j}
    __shared__ int    s_ta[TM];
    __shared__ float  s_sqa[TM];
    __shared__ double s_rt[8], s_rc[8];
    __shared__ int    s_last;

    const int tid  = threadIdx.x;
    const int lane = tid & 31;
    const int wid  = tid >> 5;
    const int warp_m = (wid & 3) * 32;
    const int warp_n = (wid >> 2) * 64;
    const int g = lane >> 2, tq = lane & 3;
    const int is64 = g_is64;
    const unsigned sbase = smem_u32(s_all);

    // ldmatrix lane-address bases (halfs)
    const unsigned a_lm = sbase + (unsigned)((warp_m + (lane & 15)) * BSTRIDE_H + (lane >> 4) * 8) * 2u;
    const unsigned b_lm_off = (unsigned)((warp_n + (lane & 7) + 8 * (lane >> 4)) * BSTRIDE_H
                                         + ((lane >> 3) & 1) * 8) * 2u;

    // ---- first tile (i,j) of this CTA ----
    int T0 = blockIdx.x * TPC;
    int ti = 0, rem = T0;
    while (rem >= S_STRIPS - ti) { rem -= S_STRIPS - ti; ti++; }
    int tj = ti + rem;

    __half* s_a = s_all;

    {
        const uint4* Xu = reinterpret_cast<const uint4*>(g_xh);
        for (int e = tid; e < TM * 16; e += 256) {
            int n = e >> 4, q = e & 15;
            *reinterpret_cast<uint4*>(&s_a[n * BSTRIDE_H + q * 8]) = Xu[(ti * TM + n) * 16 + q];
        }
        if (tid < TM) {
            int r = ti * TM + tid;
            s_ta[tid] = is64 ? (int)((const long long*)targets)[r] : ((const int*)targets)[r];
            s_sqa[tid] = g_sq[r];
        }
    }
    {
        int j0 = tj * TN;
        unsigned sb = sbase + (unsigned)BUF_H * 2u;
        for (int e = tid; e < TN * 16; e += 256) {
            int n = e >> 4, q = e & 15;
            cp16(sb + (unsigned)(n * BSTRIDE_H + q * 8) * 2u, &g_xh[(j0 + n) * D_SZ + q * 8]);
        }
        if (tid < TN) {
            int t = is64 ? (int)((const long long*)targets)[j0 + tid]
                         : ((const int*)targets)[j0 + tid];
            s_sjt[0][tid] = make_uint2(__float_as_uint(g_sq[j0 + tid]), (unsigned)t);
        }
        CP_COMMIT();
    }
    __syncthreads();

    int ta2[2][2];
    float sqa4[4];
    int reg_i = ti;
#pragma unroll
    for (int mf = 0; mf < 2; mf++)
#pragma unroll
        for (int h = 0; h < 2; h++) {
            int r = warp_m + mf * 16 + g + 8 * h;
            ta2[mf][h] = s_ta[r];
            sqa4[2 * mf + h] = s_sqa[r];
        }

    float runm[4], runn[4];
#pragma unroll
    for (int s = 0; s < 4; s++) { runm[s] = -INFINITY; runn[s] = INFINITY; }

    for (int t = 0; t < TPC; t++) {
        const int cur = t & 1, nxt = cur ^ 1;
        int ni = ti, nj = tj + 1;
        if (nj == S_STRIPS) { ni = ti + 1; nj = ni; }
        const bool last = (t == TPC - 1);
        const bool rowchg = (!last) && (ni != ti);

        if (reg_i != ti) {
            reg_i = ti;
#pragma unroll
            for (int mf = 0; mf < 2; mf++)
#pragma unroll
                for (int h = 0; h < 2; h++) {
                    int r = warp_m + mf * 16 + g + 8 * h;
                    ta2[mf][h] = s_ta[r];
                    sqa4[2 * mf + h] = s_sqa[r];
                }
        }

        if (!last) {
            int j0 = nj * TN;
            unsigned sb = sbase + (unsigned)(BUF_H * (1 + nxt)) * 2u;
            for (int e = tid; e < TN * 16; e += 256) {
                int n = e >> 4, q = e & 15;
                cp16(sb + (unsigned)(n * BSTRIDE_H + q * 8) * 2u, &g_xh[(j0 + n) * D_SZ + q * 8]);
            }
            if (tid < TN) {
                int tt = is64 ? (int)((const long long*)targets)[j0 + tid]
                              : ((const int*)targets)[j0 + tid];
                s_sjt[nxt][tid] = make_uint2(__float_as_uint(g_sq[j0 + tid]), (unsigned)tt);
            }
            CP_COMMIT();
            CP_WAIT1();
        } else {
            CP_WAIT0();
        }
        __syncthreads();

        // ---- MMA 32x64 over K=128, fragments via ldmatrix ----
        float d[2][8][4];
#pragma unroll
        for (int mf = 0; mf < 2; mf++)
#pragma unroll
            for (int nf = 0; nf < 8; nf++)
#pragma unroll
                for (int r = 0; r < 4; r++) d[mf][nf][r] = 0.0f;

        const unsigned b_lm = sbase + (unsigned)(BUF_H * (1 + cur)) * 2u + b_lm_off;
#pragma unroll
        for (int s = 0; s < 8; s++) {
            unsigned af[2][4];
            ldsm_x4(af[0][0], af[0][1], af[0][2], af[0][3], a_lm + s * 32);
            ldsm_x4(af[1][0], af[1][1], af[1][2], af[1][3],
                    a_lm + 16 * BSTRIDE_H * 2 + s * 32);
            unsigned bf[8][2];
#pragma unroll
            for (int u = 0; u < 4; u++)
                ldsm_x4(bf[2 * u][0], bf[2 * u][1], bf[2 * u + 1][0], bf[2 * u + 1][1],
                        b_lm + u * (16 * BSTRIDE_H * 2) + s * 32);
#pragma unroll
            for (int mf = 0; mf < 2; mf++)
#pragma unroll
                for (int nf = 0; nf < 8; nf++)
                    mma_f16(d[mf][nf], af[mf], bf[nf][0], bf[nf][1]);
        }

        // ---- two-sided epilogue with per-nf col flush (low reg pressure) ----
        const int j0 = tj * TN;
#pragma unroll
        for (int nf = 0; nf < 8; nf++) {
            float cm0 = -INFINITY, cm1 = -INFINITY, cn0 = INFINITY, cn1 = INFINITY;
            int colp = warp_n + nf * 8 + 2 * tq;
            uint4 pjt = *reinterpret_cast<const uint4*>(&s_sjt[cur][colp]);
            float sq0 = __uint_as_float(pjt.x); int t0 = (int)pjt.y;
            float sq1 = __uint_as_float(pjt.z); int t1 = (int)pjt.w;
#pragma unroll
            for (int mf = 0; mf < 2; mf++) {
                int s0 = 2 * mf, s1 = 2 * mf + 1;
                {
                    float vr = fmaf(-2.0f, d[mf][nf][0], sq0);
                    float vc = fmaf(-2.0f, d[mf][nf][0], sqa4[s0]);
                    if (t0 == ta2[mf][0]) { runm[s0] = fmaxf(runm[s0], vr); cm0 = fmaxf(cm0, vc); }
                    else                  { runn[s0] = fminf(runn[s0], vr); cn0 = fminf(cn0, vc); }
                }
                {
                    float vr = fmaf(-2.0f, d[mf][nf][1], sq1);
                    float vc = fmaf(-2.0f, d[mf][nf][1], sqa4[s0]);
                    if (t1 == ta2[mf][0]) { runm[s0] = fmaxf(runm[s0], vr); cm1 = fmaxf(cm1, vc); }
                    else                  { runn[s0] = fminf(runn[s0], vr); cn1 = fminf(cn1, vc); }
                }
                {
                    float vr = fmaf(-2.0f, d[mf][nf][2], sq0);
                    float vc = fmaf(-2.0f, d[mf][nf][2], sqa4[s1]);
                    if (t0 == ta2[mf][1]) { runm[s1] = fmaxf(runm[s1], vr); cm0 = fmaxf(cm0, vc); }
                    else                  { runn[s1] = fminf(runn[s1], vr); cn0 = fminf(cn0, vc); }
                }
                {
                    float vr = fmaf(-2.0f, d[mf][nf][3], sq1);
                    float vc = fmaf(-2.0f, d[mf][nf][3], sqa4[s1]);
                    if (t1 == ta2[mf][1]) { runm[s1] = fmaxf(runm[s1], vr); cm1 = fmaxf(cm1, vc); }
                    else                  { runn[s1] = fminf(runn[s1], vr); cn1 = fminf(cn1, vc); }
                }
            }
            // reduce this nf's two columns over the 8 g-lanes, then atomics
            cm0 = fmaxf(cm0, __shfl_xor_sync(0xffffffffu, cm0, 4));
            cm0 = fmaxf(cm0, __shfl_xor_sync(0xffffffffu, cm0, 8));
            cm0 = fmaxf(cm0, __shfl_xor_sync(0xffffffffu, cm0, 16));
            cn0 = fminf(cn0, __shfl_xor_sync(0xffffffffu, cn0, 4));
            cn0 = fminf(cn0, __shfl_xor_sync(0xffffffffu, cn0, 8));
            cn0 = fminf(cn0, __shfl_xor_sync(0xffffffffu, cn0, 16));
            cm1 = fmaxf(cm1, __shfl_xor_sync(0xffffffffu, cm1, 4));
            cm1 = fmaxf(cm1, __shfl_xor_sync(0xffffffffu, cm1, 8));
            cm1 = fmaxf(cm1, __shfl_xor_sync(0xffffffffu, cm1, 16));
            cn1 = fminf(cn1, __shfl_xor_sync(0xffffffffu, cn1, 4));
            cn1 = fminf(cn1, __shfl_xor_sync(0xffffffffu, cn1, 8));
            cn1 = fminf(cn1, __shfl_xor_sync(0xffffffffu, cn1, 16));
            if (lane < 4) {
                int gc = j0 + warp_n + nf * 8 + 2 * lane;
                atomicMax(&g_pm[gc], encf(cm0));
                atomicMin(&g_pn[gc], encf(cn0));
                atomicMax(&g_pm[gc + 1], encf(cm1));
                atomicMin(&g_pn[gc + 1], encf(cn1));
            }
        }

        // ---- row flush on strip change / end ----
        if (last || rowchg) {
            const int i0 = ti * TM;
#pragma unroll
            for (int slot = 0; slot < 4; slot++) {
                float m = runm[slot], n = runn[slot];
                m = fmaxf(m, __shfl_xor_sync(0xffffffffu, m, 1));
                m = fmaxf(m, __shfl_xor_sync(0xffffffffu, m, 2));
                n = fminf(n, __shfl_xor_sync(0xffffffffu, n, 1));
                n = fminf(n, __shfl_xor_sync(0xffffffffu, n, 2));
                if (tq == 0) {
                    int r = i0 + warp_m + (slot >> 1) * 16 + g + 8 * (slot & 1);
                    atomicMax(&g_pm[r], encf(m));
                    atomicMin(&g_pn[r], encf(n));
                }
                runm[slot] = -INFINITY; runn[slot] = INFINITY;
            }
        }
        if (rowchg) {
            __syncthreads();
            const uint4* Xu = reinterpret_cast<const uint4*>(g_xh);
            for (int e = tid; e < TM * 16; e += 256) {
                int n = e >> 4, q = e & 15;
                *reinterpret_cast<uint4*>(&s_a[n * BSTRIDE_H + q * 8]) = Xu[(ni * TM + n) * 16 + q];
            }
            if (tid < TM) {
                int r = ni * TM + tid;
                s_ta[tid] = is64 ? (int)((const long long*)targets)[r] : ((const int*)targets)[r];
                s_sqa[tid] = g_sq[r];
            }
        }
        __syncthreads();
        ti = ni; tj = nj;
    }

    // ---- last-CTA fused finalize ----
    if (tid == 0) {
        __threadfence();
        unsigned tk = atomicAdd(&g_done, 1u);
        s_last = (tk == NCTA - 1) ? 1 : 0;
    }
    __syncthreads();
    if (s_last) {
        __threadfence();
        double st = 0.0, sc = 0.0;
#pragma unroll
        for (int a = tid; a < B_SZ; a += 256) {
            float m = decf(g_pm[a]);
            float n = decf(g_pn[a]);
            float sqi = g_sq[a];
            float dap = sqrtf(fmaxf(sqi + m, 1e-12f));
            float dan = sqrtf(fmaxf(sqi + n, 1e-12f));
            st += (double)fmaxf(dap - dan + 0.3f, 0.0f);
            sc += (double)g_ce[a];
        }
#pragma unroll
        for (int o = 16; o; o >>= 1) {
            st += __shfl_down_sync(0xffffffffu, st, o);
            sc += __shfl_down_sync(0xffffffffu, sc, o);
        }
        if (lane == 0) { s_rt[wid] = st; s_rc[wid] = sc; }
        __syncthreads();
        if (tid == 0) {
            double t0 = 0.0, c0 = 0.0;
#pragma unroll
            for (int w = 0; w < 8; w++) { t0 += s_rt[w]; c0 += s_rc[w]; }
            const float LAM = 0.25f;
            const float TAU = logf(128.0f);
            float ce = (float)(c0 / (double)B_SZ);
            float l  = (float)(t0 / (double)B_SZ);
            float e1 = expf(1.0f);
            float z = 0.5f * fmaxf(-2.0f / e1, (l - TAU) / LAM);
            float pv = sqrtf(fmaxf(2.0f * (e1 * z + 1.0f), 0.0f));
            float wn = -1.0f + pv - pv * pv * (1.0f / 3.0f) + (11.0f / 72.0f) * pv * pv * pv;
            float w = (z < 0.0f) ? wn : log1pf(fmaxf(z, 0.0f));
#pragma unroll
            for (int it = 0; it < 8; it++) {
                float ew = expf(w);
                float f = fmaf(w, ew, -z);
                float wp1 = w + 1.0f;
                w = w - f / (ew * wp1 - (w + 2.0f) * f / (2.0f * wp1));
            }
            float sigma = expf(-w);
            float ls = logf(sigma);
            float loss = (ce - TAU) * sigma + LAM * ls * ls;
            out[0] = loss / (float)B_SZ;
        }
    }
}

extern "C" void kernel_launch(void* const* d_in, const int* in_sizes, int n_in,
                              void* d_out, int out_size) {
    const float* logits = (const float*)d_in[0];
    const void* targets = d_in[1];
    float* out = (float*)d_out;
    (void)in_sizes; (void)n_in; (void)out_size;

    const int smem_bytes = 3 * BUF_H * (int)sizeof(__half);   // 104448
    cudaFuncSetAttribute(triplet_mma_kernel, cudaFuncAttributeMaxDynamicSharedMemorySize,
                         smem_bytes);

    detect_kernel<<<1, 512>>>((const int*)targets);
    rowstats_kernel<<<B_SZ / 8, 256>>>(logits, targets);
    triplet_mma_kernel<<<NCTA, 256, smem_bytes>>>(targets, out);
}